// round 7
// baseline (speedup 1.0000x reference)
#include <cuda_runtime.h>
#include <cuda.h>
#include <cuda_fp16.h>
#include <math.h>
#include <cstdint>

#define NN   20000
#define EE   320000
#define ETOT 340000
#define FIN  384
#define F1   1024
#define HH1  4
#define HD   256
#define F2   256
#define PHID 128

// ---------------- scratch (static device globals; no runtime alloc) ----------
__device__ float g_h1[(size_t)NN * F1];
__device__ float g_h2[(size_t)NN * F2];
__device__ float g_y [(size_t)NN * PHID];
__device__ float g_ss1[NN * HH1];
__device__ float g_sd1[NN * HH1];
__device__ float g_ss2[NN];
__device__ float g_sd2[NN];
__device__ int   g_deg[NN];
__device__ int   g_off[NN + 1];
__device__ int   g_cur[NN];
__device__ int   g_csrc[ETOT];
// fp16 operand/gather planes (A row-major [M,K]; B transposed [N,K])
__device__ __align__(128) __half g_xh [(size_t)NN * FIN];
__device__ __align__(128) __half g_w1h[(size_t)F1 * FIN];
__device__ __align__(128) __half g_h1h[(size_t)NN * F1];   // fp16 copy of h1 (gather)
__device__ __align__(128) __half g_o1h[(size_t)NN * F1];   // agg1 output (GEMM2 A)
__device__ __align__(128) __half g_w2h[(size_t)F2 * F1];
__device__ __align__(128) __half g_h2h[(size_t)NN * F2];   // fp16 copy of h2 (gather)
__device__ __align__(128) __half g_hh [(size_t)NN * F2];   // final h fp16 (GEMM3 A)
__device__ __align__(128) __half g_wph[(size_t)PHID * F2];

// ---------------- helpers ----------------
__device__ __forceinline__ uint32_t smem_u32(const void* p) {
    uint32_t a;
    asm("{ .reg .u64 t; cvta.to.shared.u64 t, %1; cvt.u32.u64 %0, t; }" : "=r"(a) : "l"(p));
    return a;
}
__device__ __forceinline__ void ldm4(uint32_t* r, uint32_t a) {
    asm volatile("ldmatrix.sync.aligned.m8n8.x4.shared.b16 {%0,%1,%2,%3}, [%4];"
                 : "=r"(r[0]), "=r"(r[1]), "=r"(r[2]), "=r"(r[3]) : "r"(a));
}
__device__ __forceinline__ void mma16816(float* c, const uint32_t* a, uint32_t b0, uint32_t b1) {
    asm volatile("mma.sync.aligned.m16n8k16.row.col.f32.f16.f16.f32 "
                 "{%0,%1,%2,%3}, {%4,%5,%6,%7}, {%8,%9}, {%0,%1,%2,%3};"
                 : "+f"(c[0]), "+f"(c[1]), "+f"(c[2]), "+f"(c[3])
                 : "r"(a[0]), "r"(a[1]), "r"(a[2]), "r"(a[3]), "r"(b0), "r"(b1));
}
#define MBARRIER_INIT(mb, c) \
    asm volatile("mbarrier.init.shared.b64 [%0], %1;" :: "r"((uint32_t)(mb)), "r"((uint32_t)(c)) : "memory")
#define MBARRIER_EXPECT_TX(mb, b) \
    asm volatile("mbarrier.arrive.expect_tx.shared.b64 _, [%0], %1;" \
                 :: "r"((uint32_t)(mb)), "r"((uint32_t)(b)) : "memory")
#define MBARRIER_WAIT_PARITY(mb, par) do { \
    uint32_t _m = (uint32_t)(mb), _p = (uint32_t)(par), _d; \
    asm volatile("{\n\t.reg .pred p;\n\t" \
        "mbarrier.try_wait.parity.acquire.cta.shared::cta.b64 p, [%1], %2;\n\t" \
        "selp.b32 %0, 1, 0, p;\n\t}" : "=r"(_d) : "r"(_m), "r"(_p) : "memory"); \
    if (!_d) { \
        asm volatile("{\n\t.reg .pred P1;\n\tWL_%=:\n\t" \
            "mbarrier.try_wait.parity.acquire.cta.shared::cta.b64 P1, [%0], %1, 0x989680;\n\t" \
            "@P1 bra.uni WD_%=;\n\tbra.uni WL_%=;\n\tWD_%=:\n\t}" \
            :: "r"(_m), "r"(_p) : "memory"); \
    } } while (0)
__device__ __forceinline__ void tma2d(uint32_t dst, const void* map, int x, int y, uint32_t mb) {
    asm volatile(
        "cp.async.bulk.tensor.2d.shared::cta.global.tile.mbarrier::complete_tx::bytes "
        "[%0], [%1, {%2, %3}], [%4];"
        :: "r"(dst), "l"(map), "r"(x), "r"(y), "r"(mb) : "memory");
}
#define SW128(o) ((o) ^ (((o) >> 3) & 0x70u))

// ---------------- fp16 cast kernels ----------------
__global__ void k_cast(const float* __restrict__ in, __half* __restrict__ o, int total) {
    int i = blockIdx.x * blockDim.x + threadIdx.x;
    if (i < total) o[i] = __float2half_rn(in[i]);
}
// W [K,N] fp32 -> [N,K] fp16 (transposed)
__global__ void k_castT(const float* __restrict__ W, __half* __restrict__ o, int K, int N) {
    int i = blockIdx.x * blockDim.x + threadIdx.x;
    if (i >= K * N) return;
    int k = i / N, n = i % N;
    o[(size_t)n * K + k] = __float2half_rn(W[i]);
}

// ============== TMA HMMA GEMM: C[M,N] = A[M,K] @ B[N,K]^T ====================
// fp16 in, fp32 accum/out; optional fp16 copy Ch. CTA 128x128, BK=64 (SW128),
// 3-stage TMA pipeline, 8 warps (32x64 each), 2 CTAs/SM.
#define TG_STAGE 32768
#define TG_SMEM (1024 + 3 * TG_STAGE)

__global__ void __launch_bounds__(256, 2)
hgemm_tma(const __grid_constant__ CUtensorMap mA,
          const __grid_constant__ CUtensorMap mB,
          float* __restrict__ C, __half* __restrict__ Ch, int M, int N, int K) {
    extern __shared__ unsigned char smraw[];
    const uint32_t base0 = (smem_u32(smraw) + 1023u) & ~1023u;
    const uint32_t mbb = base0;            // 3 mbarriers
    const uint32_t tile0 = base0 + 1024;   // 3 stages x 32KB
    const int tid = threadIdx.x, wid = tid >> 5, lane = tid & 31;
    const int bm = blockIdx.y * 128, bn = blockIdx.x * 128;
    const int wr = (wid >> 1) * 32, wn = (wid & 1) * 64;
    const int nc = K >> 6;

    if (tid == 0) {
        MBARRIER_INIT(mbb + 0, 1);
        MBARRIER_INIT(mbb + 8, 1);
        MBARRIER_INIT(mbb + 16, 1);
    }
    __syncthreads();

    if (tid == 0) {
#pragma unroll
        for (int s = 0; s < 2; s++) {
            uint32_t mb = mbb + 8u * s;
            uint32_t t = tile0 + (uint32_t)s * TG_STAGE;
            MBARRIER_EXPECT_TX(mb, TG_STAGE);
            tma2d(t,          &mA, s * 64, bm, mb);
            tma2d(t + 16384u, &mB, s * 64, bn, mb);
        }
    }

    float acc[2][8][4];
#pragma unroll
    for (int a = 0; a < 2; a++)
#pragma unroll
        for (int b = 0; b < 8; b++)
#pragma unroll
            for (int c = 0; c < 4; c++) acc[a][b][c] = 0.f;

    for (int i = 0; i < nc; i++) {
        const int b = i % 3;
        MBARRIER_WAIT_PARITY(mbb + 8u * b, (i / 3) & 1);
        __syncthreads();
        if (tid == 0 && i + 2 < nc) {
            const int nb = (i + 2) % 3;
            uint32_t mb = mbb + 8u * nb;
            uint32_t t = tile0 + (uint32_t)nb * TG_STAGE;
            MBARRIER_EXPECT_TX(mb, TG_STAGE);
            tma2d(t,          &mA, (i + 2) * 64, bm, mb);
            tma2d(t + 16384u, &mB, (i + 2) * 64, bn, mb);
        }

        const uint32_t tA = tile0 + (uint32_t)b * TG_STAGE;
        const uint32_t tB = tA + 16384u;
        const int gq = lane >> 3;
#pragma unroll
        for (int ks = 0; ks < 4; ks++) {
            uint32_t ar[2][4], br[4][4];
#pragma unroll
            for (int mt = 0; mt < 2; mt++) {
                uint32_t lin = (uint32_t)(wr + mt * 16 + (lane & 15)) * 128u
                             + (uint32_t)(ks * 32 + (lane >> 4) * 16);
                ldm4(ar[mt], tA + SW128(lin));
            }
#pragma unroll
            for (int bt = 0; bt < 4; bt++) {
                uint32_t lin = (uint32_t)(wn + bt * 16 + ((gq >> 1) << 3) + (lane & 7)) * 128u
                             + (uint32_t)(ks * 32 + (gq & 1) * 16);
                ldm4(br[bt], tB + SW128(lin));
            }
#pragma unroll
            for (int mt = 0; mt < 2; mt++)
#pragma unroll
                for (int j = 0; j < 8; j++) {
                    const int bt = j >> 1, p0 = (j & 1) * 2;
                    mma16816(acc[mt][j], ar[mt], br[bt][p0], br[bt][p0 + 1]);
                }
        }
    }

    // epilogue: fp32 C, optional fp16 copy
#pragma unroll
    for (int mt = 0; mt < 2; mt++) {
        int m0 = bm + wr + mt * 16 + (lane >> 2);
#pragma unroll
        for (int j = 0; j < 8; j++) {
            int n0 = bn + wn + j * 8 + (lane & 3) * 2;
            if (m0 < M) {
                *(float2*)&C[(size_t)m0 * N + n0] = make_float2(acc[mt][j][0], acc[mt][j][1]);
                if (Ch) *(__half2*)&Ch[(size_t)m0 * N + n0] =
                    __floats2half2_rn(acc[mt][j][0], acc[mt][j][1]);
            }
            if (m0 + 8 < M) {
                *(float2*)&C[(size_t)(m0 + 8) * N + n0] = make_float2(acc[mt][j][2], acc[mt][j][3]);
                if (Ch) *(__half2*)&Ch[(size_t)(m0 + 8) * N + n0] =
                    __floats2half2_rn(acc[mt][j][2], acc[mt][j][3]);
            }
        }
    }
}

// ---------------- attention logits (fp32 feat) ----------------
__global__ void k_slogits(const float* __restrict__ feat, const float* __restrict__ asrc,
                          const float* __restrict__ adst, float* __restrict__ ss,
                          float* __restrict__ sd, int n, int H, int C) {
    int w = (blockIdx.x * blockDim.x + threadIdx.x) >> 5;
    int lane = threadIdx.x & 31;
    if (w >= n * H) return;
    int node = w / H, h = w % H;
    const float* row = &feat[(size_t)node * H * C + h * C];
    float a = 0.f, b = 0.f;
    for (int c = lane; c < C; c += 32) {
        float v = row[c];
        a += v * asrc[h * C + c];
        b += v * adst[h * C + c];
    }
#pragma unroll
    for (int o = 16; o; o >>= 1) {
        a += __shfl_xor_sync(0xffffffffu, a, o);
        b += __shfl_xor_sync(0xffffffffu, b, o);
    }
    if (lane == 0) { ss[w] = a; sd[w] = b; }
}

// ---------------- CSR build ----------------
__global__ void k_deg_init(int n) {
    int i = blockIdx.x * blockDim.x + threadIdx.x;
    if (i < n) g_deg[i] = 1;
}
__global__ void k_deg_count(const int* __restrict__ dst, int e) {
    int i = blockIdx.x * blockDim.x + threadIdx.x;
    if (i < e) atomicAdd(&g_deg[dst[i]], 1);
}
__global__ void k_scan(int n) {
    __shared__ int sums[1024];
    int tid = threadIdx.x;
    int chunk = (n + 1023) / 1024;
    int lo = tid * chunk, hi = min(lo + chunk, n);
    int s = 0;
    for (int i = lo; i < hi; i++) s += g_deg[i];
    sums[tid] = s;
    __syncthreads();
    for (int d = 1; d < 1024; d <<= 1) {
        int v = (tid >= d) ? sums[tid - d] : 0;
        __syncthreads();
        sums[tid] += v;
        __syncthreads();
    }
    int base = (tid == 0) ? 0 : sums[tid - 1];
    for (int i = lo; i < hi; i++) {
        g_off[i] = base;
        g_cur[i] = base;
        base += g_deg[i];
    }
    if (tid == 1023) g_off[n] = sums[1023];
}
__global__ void k_fill(const int* __restrict__ src, const int* __restrict__ dst, int e, int n) {
    int i = blockIdx.x * blockDim.x + threadIdx.x;
    if (i >= e + n) return;
    int s, d;
    if (i < e) { s = src[i]; d = dst[i]; }
    else       { s = i - e;  d = i - e; }
    int pos = atomicAdd(&g_cur[d], 1);
    g_csrc[pos] = s;
}

// ---------------- per-dst softmax + aggregation (fp16 gather) ---------------
__device__ __forceinline__ float lrelu(float x) { return x > 0.f ? x : 0.2f * x; }

template <int H, int C, int PC>   // PC = H*C/256; chunk CH = 256/H edges
__global__ void __launch_bounds__(256)
k_agg(const __half* __restrict__ feat, const float* __restrict__ ss,
      const float* __restrict__ sd, const float* __restrict__ bias,
      float* __restrict__ out, __half* __restrict__ oh) {
    constexpr int CH = 256 / H;
    const int d = blockIdx.x;
    const int base = g_off[d], deg = g_off[d + 1] - base;
    __shared__ float s_m[H], s_inv[H];
    __shared__ float s_w[CH * H];
    __shared__ int   s_idx[CH];
    const int t = threadIdx.x;
    const int wid = t >> 5, lane = t & 31;

    if (wid < H) {
        const int h = wid;
        float sdv = sd[d * H + h];
        float mx = -1e30f;
        for (int j = lane; j < deg; j += 32) {
            int s = g_csrc[base + j];
            mx = fmaxf(mx, lrelu(ss[s * H + h] + sdv));
        }
#pragma unroll
        for (int o = 16; o; o >>= 1) mx = fmaxf(mx, __shfl_xor_sync(0xffffffffu, mx, o));
        float sm = 0.f;
        for (int j = lane; j < deg; j += 32) {
            int s = g_csrc[base + j];
            sm += expf(lrelu(ss[s * H + h] + sdv) - mx);
        }
#pragma unroll
        for (int o = 16; o; o >>= 1) sm += __shfl_xor_sync(0xffffffffu, sm, o);
        if (lane == 0) { s_m[h] = mx; s_inv[h] = 1.f / (sm + 1e-16f); }
    }
    __syncthreads();

    const int hh = (t * PC) / C;
    float acc[PC];
#pragma unroll
    for (int k = 0; k < PC; k++) acc[k] = 0.f;

    for (int j0 = 0; j0 < deg; j0 += CH) {
        const int cnt = min(CH, deg - j0);
        {
            const int jj = (H == 1) ? t : (t >> 2);
            const int h  = (H == 1) ? 0 : (t & 3);
            if (jj < cnt) {
                int s = g_csrc[base + j0 + jj];
                if (h == 0) s_idx[jj] = s;
                float w = expf(lrelu(ss[s * H + h] + sd[d * H + h]) - s_m[h]) * s_inv[h];
                s_w[jj * H + h] = w;
            }
        }
        __syncthreads();
        for (int j = 0; j < cnt; j++) {
            int s = s_idx[j];
            float w = s_w[j * H + hh];
            if (PC == 4) {
                uint2 v = *(const uint2*)&feat[(size_t)s * H * C + t * 4];
                float2 f0 = __half22float2(*(const __half2*)&v.x);
                float2 f1 = __half22float2(*(const __half2*)&v.y);
                acc[0] += f0.x * w; acc[1] += f0.y * w;
                acc[2] += f1.x * w; acc[3] += f1.y * w;
            } else {
                acc[0] += __half2float(feat[(size_t)s * C + t]) * w;
            }
        }
        __syncthreads();
    }

    const int HC = H * C;
#pragma unroll
    for (int k = 0; k < PC; k++) {
        int c = t * PC + k;
        float v = acc[k] + bias[c];
        v = v > 0.f ? v : expm1f(v);
        if (out) out[(size_t)d * HC + c] = v;
        oh[(size_t)d * HC + c] = __float2half_rn(v);
    }
}

// ---------------- graph mean + influence head ----------------
__global__ void k_zero_gf(float* gf) { gf[threadIdx.x] = 0.f; }
__global__ void k_colsum(const float* __restrict__ h, float* __restrict__ gf) {
    float acc = 0.f;
    int t = threadIdx.x;
    for (int r = blockIdx.x; r < NN; r += gridDim.x) acc += h[(size_t)r * F2 + t];
    atomicAdd(&gf[t], acc);
}
__global__ void k_scale_gf(float* gf) { gf[threadIdx.x] *= (1.0f / (float)NN); }

__global__ void k_infl(const float* __restrict__ y, const float* __restrict__ bp1,
                       const float* __restrict__ wp2, const float* __restrict__ bp2,
                       float* __restrict__ infl) {
    int w = (blockIdx.x * blockDim.x + threadIdx.x) >> 5;
    int lane = threadIdx.x & 31;
    if (w >= NN) return;
    float acc = 0.f;
    for (int j = lane; j < PHID; j += 32) {
        float v = y[(size_t)w * PHID + j] + bp1[j];
        v = v > 0.f ? v : 0.f;
        acc += v * wp2[j];
    }
#pragma unroll
    for (int o = 16; o; o >>= 1) acc += __shfl_xor_sync(0xffffffffu, acc, o);
    if (lane == 0) infl[w] = 1.f / (1.f + expf(-(acc + bp2[0])));
}

// ---------------- host: tensor-map builder ----------------
typedef CUresult (*PFN_encodeTiled)(
    CUtensorMap*, CUtensorMapDataType, cuuint32_t, void*,
    const cuuint64_t*, const cuuint64_t*, const cuuint32_t*, const cuuint32_t*,
    CUtensorMapInterleave, CUtensorMapSwizzle, CUtensorMapL2promotion,
    CUtensorMapFloatOOBfill);

static CUtensorMap make_map(PFN_encodeTiled enc, void* base, int K, int rows) {
    CUtensorMap m;
    cuuint64_t dims[2]    = {(cuuint64_t)K, (cuuint64_t)rows};
    cuuint64_t strides[1] = {(cuuint64_t)K * 2};
    cuuint32_t box[2]     = {64, 128};
    cuuint32_t es[2]      = {1, 1};
    enc(&m, CU_TENSOR_MAP_DATA_TYPE_FLOAT16, 2, base, dims, strides, box, es,
        CU_TENSOR_MAP_INTERLEAVE_NONE, CU_TENSOR_MAP_SWIZZLE_128B,
        CU_TENSOR_MAP_L2_PROMOTION_L2_128B, CU_TENSOR_MAP_FLOAT_OOB_FILL_NONE);
    return m;
}

// ---------------- launch ----------------
extern "C" void kernel_launch(void* const* d_in, const int* in_sizes, int n_in,
                              void* d_out, int out_size) {
    const float* x   = (const float*)d_in[0];
    const int*   eidx = (const int*)d_in[1];
    const float* W1  = (const float*)d_in[2];
    const float* as1 = (const float*)d_in[3];
    const float* ad1 = (const float*)d_in[4];
    const float* b1  = (const float*)d_in[5];
    const float* W2  = (const float*)d_in[6];
    const float* as2 = (const float*)d_in[7];
    const float* ad2 = (const float*)d_in[8];
    const float* b2  = (const float*)d_in[9];
    const float* Wp1 = (const float*)d_in[10];
    const float* bp1 = (const float*)d_in[11];
    const float* Wp2 = (const float*)d_in[12];
    const float* bp2 = (const float*)d_in[13];

    const int* src = eidx;
    const int* dst = eidx + EE;

    float* out   = (float*)d_out;
    float* out_h = out;
    float* out_g = out + (size_t)NN * F2;
    float* out_i = out_g + F2;

    float *p_h1, *p_h2, *p_y, *p_ss1, *p_sd1, *p_ss2, *p_sd2;
    __half *p_xh, *p_w1h, *p_h1h, *p_o1h, *p_w2h, *p_h2h, *p_hh, *p_wph;
    cudaGetSymbolAddress((void**)&p_h1, g_h1);
    cudaGetSymbolAddress((void**)&p_h2, g_h2);
    cudaGetSymbolAddress((void**)&p_y,  g_y);
    cudaGetSymbolAddress((void**)&p_ss1, g_ss1);
    cudaGetSymbolAddress((void**)&p_sd1, g_sd1);
    cudaGetSymbolAddress((void**)&p_ss2, g_ss2);
    cudaGetSymbolAddress((void**)&p_sd2, g_sd2);
    cudaGetSymbolAddress((void**)&p_xh,  g_xh);
    cudaGetSymbolAddress((void**)&p_w1h, g_w1h);
    cudaGetSymbolAddress((void**)&p_h1h, g_h1h);
    cudaGetSymbolAddress((void**)&p_o1h, g_o1h);
    cudaGetSymbolAddress((void**)&p_w2h, g_w2h);
    cudaGetSymbolAddress((void**)&p_h2h, g_h2h);
    cudaGetSymbolAddress((void**)&p_hh,  g_hh);
    cudaGetSymbolAddress((void**)&p_wph, g_wph);

    PFN_encodeTiled enc = nullptr;
    cudaGetDriverEntryPoint("cuTensorMapEncodeTiled", (void**)&enc, cudaEnableDefault);

    CUtensorMap mA1 = make_map(enc, p_xh,  FIN, NN);
    CUtensorMap mB1 = make_map(enc, p_w1h, FIN, F1);
    CUtensorMap mA2 = make_map(enc, p_o1h, F1,  NN);
    CUtensorMap mB2 = make_map(enc, p_w2h, F1,  F2);
    CUtensorMap mA3 = make_map(enc, p_hh,  F2,  NN);
    CUtensorMap mB3 = make_map(enc, p_wph, F2, PHID);

    cudaFuncSetAttribute(hgemm_tma, cudaFuncAttributeMaxDynamicSharedMemorySize, TG_SMEM);

    const int MR = (NN + 127) / 128;  // 157 row tiles

    k_cast <<<(NN * FIN + 255) / 256, 256>>>(x, p_xh, NN * FIN);
    k_castT<<<(FIN * F1 + 255) / 256, 256>>>(W1, p_w1h, FIN, F1);
    k_castT<<<(F1 * F2 + 255) / 256, 256>>>(W2, p_w2h, F1, F2);

    // GEMM1: h1 = x @ W1 (fp32 + fp16 planes)
    hgemm_tma<<<dim3(F1 / 128, MR), 256, TG_SMEM>>>(mA1, mB1, p_h1, p_h1h, NN, F1, FIN);

    k_castT<<<(F2 * PHID + 255) / 256, 256>>>(Wp1, p_wph, F2, PHID);

    // attention logits layer 1 (fp32 h1)
    k_slogits<<<(NN * HH1 * 32 + 255) / 256, 256>>>(p_h1, as1, ad1, p_ss1, p_sd1, NN, HH1, HD);

    // CSR build
    k_deg_init <<<(NN + 255) / 256, 256>>>(NN);
    k_deg_count<<<(EE + 255) / 256, 256>>>(dst, EE);
    k_scan<<<1, 1024>>>(NN);
    k_fill<<<(ETOT + 255) / 256, 256>>>(src, dst, EE, NN);

    // layer 1 softmax-aggregate (fp16 gather) + bias + ELU -> fp16 plane
    k_agg<HH1, HD, 4><<<NN, 256>>>(p_h1h, p_ss1, p_sd1, b1, nullptr, p_o1h);

    // GEMM2: h2 = o1 @ W2 (fp32 + fp16 planes)
    hgemm_tma<<<dim3(F2 / 128, MR), 256, TG_SMEM>>>(mA2, mB2, p_h2, p_h2h, NN, F2, F1);

    // attention logits layer 2 (fp32 h2)
    k_slogits<<<(NN * 32 + 255) / 256, 256>>>(p_h2, as2, ad2, p_ss2, p_sd2, NN, 1, HD);

    // layer 2 softmax-aggregate (fp16 gather) -> fp32 out_h + fp16 plane
    k_agg<1, F2, 1><<<NN, 256>>>(p_h2h, p_ss2, p_sd2, b2, out_h, p_hh);

    // graph mean
    k_zero_gf<<<1, F2>>>(out_g);
    k_colsum<<<160, F2>>>(out_h, out_g);
    k_scale_gf<<<1, F2>>>(out_g);

    // influence head
    hgemm_tma<<<dim3(PHID / 128, MR), 256, TG_SMEM>>>(mA3, mB3, p_y, nullptr, NN, PHID, F2);
    k_infl<<<(NN * 32 + 255) / 256, 256>>>(p_y, bp1, Wp2, bp2, out_i);
}

// round 8
// speedup vs baseline: 1.0740x; 1.0740x over previous
#include <cuda_runtime.h>
#include <cuda.h>
#include <cuda_fp16.h>
#include <math.h>
#include <cstdint>

#define NN   20000
#define EE   320000
#define ETOT 340000
#define FIN  384
#define F1   1024
#define HH1  4
#define HD   256
#define F2   256
#define PHID 128

// ---------------- scratch (static device globals; no runtime alloc) ----------
__device__ float g_h1[(size_t)NN * F1];
__device__ float g_h2[(size_t)NN * F2];
__device__ float g_y [(size_t)NN * PHID];
__device__ float g_ss1[NN * HH1];
__device__ float g_sd1[NN * HH1];
__device__ float g_ss2[NN];
__device__ float g_sd2[NN];
__device__ int   g_deg[NN];
__device__ int   g_off[NN + 1];
__device__ int   g_cur[NN];
__device__ int   g_csrc[ETOT];
// fp16 operand planes (A row-major [M,K]; B transposed [N,K])
__device__ __align__(128) __half g_xh [(size_t)NN * FIN];
__device__ __align__(128) __half g_w1h[(size_t)F1 * FIN];
__device__ __align__(128) __half g_o1h[(size_t)NN * F1];
__device__ __align__(128) __half g_w2h[(size_t)F2 * F1];
__device__ __align__(128) __half g_hh [(size_t)NN * F2];
__device__ __align__(128) __half g_wph[(size_t)PHID * F2];

// ---------------- helpers ----------------
__device__ __forceinline__ uint32_t smem_u32(const void* p) {
    uint32_t a;
    asm("{ .reg .u64 t; cvta.to.shared.u64 t, %1; cvt.u32.u64 %0, t; }" : "=r"(a) : "l"(p));
    return a;
}
__device__ __forceinline__ void ldm4(uint32_t* r, uint32_t a) {
    asm volatile("ldmatrix.sync.aligned.m8n8.x4.shared.b16 {%0,%1,%2,%3}, [%4];"
                 : "=r"(r[0]), "=r"(r[1]), "=r"(r[2]), "=r"(r[3]) : "r"(a));
}
__device__ __forceinline__ void mma16816(float* c, const uint32_t* a, uint32_t b0, uint32_t b1) {
    asm volatile("mma.sync.aligned.m16n8k16.row.col.f32.f16.f16.f32 "
                 "{%0,%1,%2,%3}, {%4,%5,%6,%7}, {%8,%9}, {%0,%1,%2,%3};"
                 : "+f"(c[0]), "+f"(c[1]), "+f"(c[2]), "+f"(c[3])
                 : "r"(a[0]), "r"(a[1]), "r"(a[2]), "r"(a[3]), "r"(b0), "r"(b1));
}
#define MBARRIER_INIT(mb, c) \
    asm volatile("mbarrier.init.shared.b64 [%0], %1;" :: "r"((uint32_t)(mb)), "r"((uint32_t)(c)) : "memory")
#define MBARRIER_EXPECT_TX(mb, b) \
    asm volatile("mbarrier.arrive.expect_tx.shared.b64 _, [%0], %1;" \
                 :: "r"((uint32_t)(mb)), "r"((uint32_t)(b)) : "memory")
#define MBARRIER_WAIT_PARITY(mb, par) do { \
    uint32_t _m = (uint32_t)(mb), _p = (uint32_t)(par), _d; \
    asm volatile("{\n\t.reg .pred p;\n\t" \
        "mbarrier.try_wait.parity.acquire.cta.shared::cta.b64 p, [%1], %2;\n\t" \
        "selp.b32 %0, 1, 0, p;\n\t}" : "=r"(_d) : "r"(_m), "r"(_p) : "memory"); \
    if (!_d) { \
        asm volatile("{\n\t.reg .pred P1;\n\tWL_%=:\n\t" \
            "mbarrier.try_wait.parity.acquire.cta.shared::cta.b64 P1, [%0], %1, 0x989680;\n\t" \
            "@P1 bra.uni WD_%=;\n\tbra.uni WL_%=;\n\tWD_%=:\n\t}" \
            :: "r"(_m), "r"(_p) : "memory"); \
    } } while (0)
__device__ __forceinline__ void tma2d(uint32_t dst, const void* map, int x, int y, uint32_t mb) {
    asm volatile(
        "cp.async.bulk.tensor.2d.shared::cta.global.tile.mbarrier::complete_tx::bytes "
        "[%0], [%1, {%2, %3}], [%4];"
        :: "r"(dst), "l"(map), "r"(x), "r"(y), "r"(mb) : "memory");
}
#define SW128(o) ((o) ^ (((o) >> 3) & 0x70u))

// ---------------- fp16 cast kernels ----------------
__global__ void k_cast(const float* __restrict__ in, __half* __restrict__ o, int total) {
    int i = blockIdx.x * blockDim.x + threadIdx.x;
    if (i < total) o[i] = __float2half_rn(in[i]);
}
// W [K,N] fp32 -> [N,K] fp16 (transposed)
__global__ void k_castT(const float* __restrict__ W, __half* __restrict__ o, int K, int N) {
    int i = blockIdx.x * blockDim.x + threadIdx.x;
    if (i >= K * N) return;
    int k = i / N, n = i % N;
    o[(size_t)n * K + k] = __float2half_rn(W[i]);
}

// ============== TMA HMMA GEMM: C[M,N] = A[M,K] @ B[N,K]^T ====================
// fp16 in, fp32 accum/out. CTA 128x128, BK=64 (SW128), 3-stage TMA pipeline,
// 8 warps (32x64 each), 2 CTAs/SM. (R6 version — no fp16 epilogue copy.)
#define TG_STAGE 32768
#define TG_SMEM (1024 + 3 * TG_STAGE)

__global__ void __launch_bounds__(256, 2)
hgemm_tma(const __grid_constant__ CUtensorMap mA,
          const __grid_constant__ CUtensorMap mB,
          float* __restrict__ C, int M, int N, int K) {
    extern __shared__ unsigned char smraw[];
    const uint32_t base0 = (smem_u32(smraw) + 1023u) & ~1023u;
    const uint32_t mbb = base0;
    const uint32_t tile0 = base0 + 1024;
    const int tid = threadIdx.x, wid = tid >> 5, lane = tid & 31;
    const int bm = blockIdx.y * 128, bn = blockIdx.x * 128;
    const int wr = (wid >> 1) * 32, wn = (wid & 1) * 64;
    const int nc = K >> 6;

    if (tid == 0) {
        MBARRIER_INIT(mbb + 0, 1);
        MBARRIER_INIT(mbb + 8, 1);
        MBARRIER_INIT(mbb + 16, 1);
    }
    __syncthreads();

    if (tid == 0) {
#pragma unroll
        for (int s = 0; s < 2; s++) {
            uint32_t mb = mbb + 8u * s;
            uint32_t t = tile0 + (uint32_t)s * TG_STAGE;
            MBARRIER_EXPECT_TX(mb, TG_STAGE);
            tma2d(t,          &mA, s * 64, bm, mb);
            tma2d(t + 16384u, &mB, s * 64, bn, mb);
        }
    }

    float acc[2][8][4];
#pragma unroll
    for (int a = 0; a < 2; a++)
#pragma unroll
        for (int b = 0; b < 8; b++)
#pragma unroll
            for (int c = 0; c < 4; c++) acc[a][b][c] = 0.f;

    for (int i = 0; i < nc; i++) {
        const int b = i % 3;
        MBARRIER_WAIT_PARITY(mbb + 8u * b, (i / 3) & 1);
        __syncthreads();
        if (tid == 0 && i + 2 < nc) {
            const int nb = (i + 2) % 3;
            uint32_t mb = mbb + 8u * nb;
            uint32_t t = tile0 + (uint32_t)nb * TG_STAGE;
            MBARRIER_EXPECT_TX(mb, TG_STAGE);
            tma2d(t,          &mA, (i + 2) * 64, bm, mb);
            tma2d(t + 16384u, &mB, (i + 2) * 64, bn, mb);
        }

        const uint32_t tA = tile0 + (uint32_t)b * TG_STAGE;
        const uint32_t tB = tA + 16384u;
        const int gq = lane >> 3;
#pragma unroll
        for (int ks = 0; ks < 4; ks++) {
            uint32_t ar[2][4], br[4][4];
#pragma unroll
            for (int mt = 0; mt < 2; mt++) {
                uint32_t lin = (uint32_t)(wr + mt * 16 + (lane & 15)) * 128u
                             + (uint32_t)(ks * 32 + (lane >> 4) * 16);
                ldm4(ar[mt], tA + SW128(lin));
            }
#pragma unroll
            for (int bt = 0; bt < 4; bt++) {
                uint32_t lin = (uint32_t)(wn + bt * 16 + ((gq >> 1) << 3) + (lane & 7)) * 128u
                             + (uint32_t)(ks * 32 + (gq & 1) * 16);
                ldm4(br[bt], tB + SW128(lin));
            }
#pragma unroll
            for (int mt = 0; mt < 2; mt++)
#pragma unroll
                for (int j = 0; j < 8; j++) {
                    const int bt = j >> 1, p0 = (j & 1) * 2;
                    mma16816(acc[mt][j], ar[mt], br[bt][p0], br[bt][p0 + 1]);
                }
        }
    }

#pragma unroll
    for (int mt = 0; mt < 2; mt++) {
        int m0 = bm + wr + mt * 16 + (lane >> 2);
#pragma unroll
        for (int j = 0; j < 8; j++) {
            int n0 = bn + wn + j * 8 + (lane & 3) * 2;
            if (m0 < M)
                *(float2*)&C[(size_t)m0 * N + n0] = make_float2(acc[mt][j][0], acc[mt][j][1]);
            if (m0 + 8 < M)
                *(float2*)&C[(size_t)(m0 + 8) * N + n0] = make_float2(acc[mt][j][2], acc[mt][j][3]);
        }
    }
}

// ---------------- attention logits (fp32 feat) ----------------
__global__ void k_slogits(const float* __restrict__ feat, const float* __restrict__ asrc,
                          const float* __restrict__ adst, float* __restrict__ ss,
                          float* __restrict__ sd, int n, int H, int C) {
    int w = (blockIdx.x * blockDim.x + threadIdx.x) >> 5;
    int lane = threadIdx.x & 31;
    if (w >= n * H) return;
    int node = w / H, h = w % H;
    const float* row = &feat[(size_t)node * H * C + h * C];
    float a = 0.f, b = 0.f;
    for (int c = lane; c < C; c += 32) {
        float v = row[c];
        a += v * asrc[h * C + c];
        b += v * adst[h * C + c];
    }
#pragma unroll
    for (int o = 16; o; o >>= 1) {
        a += __shfl_xor_sync(0xffffffffu, a, o);
        b += __shfl_xor_sync(0xffffffffu, b, o);
    }
    if (lane == 0) { ss[w] = a; sd[w] = b; }
}

// ---------------- CSR build ----------------
__global__ void k_deg_init(int n) {
    int i = blockIdx.x * blockDim.x + threadIdx.x;
    if (i < n) g_deg[i] = 1;
}
__global__ void k_deg_count(const int* __restrict__ dst, int e) {
    int i = blockIdx.x * blockDim.x + threadIdx.x;
    if (i < e) atomicAdd(&g_deg[dst[i]], 1);
}
__global__ void k_scan(int n) {
    __shared__ int sums[1024];
    int tid = threadIdx.x;
    int chunk = (n + 1023) / 1024;
    int lo = tid * chunk, hi = min(lo + chunk, n);
    int s = 0;
    for (int i = lo; i < hi; i++) s += g_deg[i];
    sums[tid] = s;
    __syncthreads();
    for (int d = 1; d < 1024; d <<= 1) {
        int v = (tid >= d) ? sums[tid - d] : 0;
        __syncthreads();
        sums[tid] += v;
        __syncthreads();
    }
    int base = (tid == 0) ? 0 : sums[tid - 1];
    for (int i = lo; i < hi; i++) {
        g_off[i] = base;
        g_cur[i] = base;
        base += g_deg[i];
    }
    if (tid == 1023) g_off[n] = sums[1023];
}
__global__ void k_fill(const int* __restrict__ src, const int* __restrict__ dst, int e, int n) {
    int i = blockIdx.x * blockDim.x + threadIdx.x;
    if (i >= e + n) return;
    int s, d;
    if (i < e) { s = src[i]; d = dst[i]; }
    else       { s = i - e;  d = i - e; }
    int pos = atomicAdd(&g_cur[d], 1);
    g_csrc[pos] = s;
}

// ---------------- per-dst softmax + aggregation + bias + ELU ----------------
// e-cache design: one gather pass caches lrelu logits for <=CAP edges in smem;
// reductions + weight conversion are LDS-only; accumulate uses 2-deep prefetch.
__device__ __forceinline__ float lrelu(float x) { return x > 0.f ? x : 0.2f * x; }

template <int H, int C, int PC>   // PC = H*C/256
__global__ void __launch_bounds__(256)
k_agg(const float* __restrict__ feat, const float* __restrict__ ss,
      const float* __restrict__ sd, const float* __restrict__ bias,
      float* __restrict__ out, __half* __restrict__ oh) {
    constexpr int CAP = 256;
    constexpr int ST  = (H == 4) ? 5 : 1;   // pad stride vs LDS conflicts
    const int d = blockIdx.x;
    const int base = g_off[d], deg = g_off[d + 1] - base;
    const int capped = min(deg, CAP);
    __shared__ float s_m[H], s_inv[H];
    __shared__ float s_e[CAP * ST];
    __shared__ int   s_idx[CAP];
    const int t = threadIdx.x, wid = t >> 5, lane = t & 31;

    // Phase A: cache src indices + raw leaky-relu logits (one gather pass)
    {
        const int jj = (H == 1) ? t : (t >> 2);
        const int h  = (H == 1) ? 0 : (t & 3);
        const float sdv = sd[d * H + h];
        for (int j0 = 0; j0 < capped; j0 += 256 / H) {
            int j = j0 + jj;
            if (j < capped) {
                int s = g_csrc[base + j];
                if (h == 0) s_idx[j] = s;
                s_e[j * ST + h] = lrelu(ss[s * H + h] + sdv);
            }
        }
    }
    __syncthreads();

    // Phase B: per-head max + denominator (warp h; LDS for cached, gather for overflow)
    if (wid < H) {
        const int h = wid;
        const float sdv = sd[d * H + h];
        float mx = -1e30f;
        for (int j = lane; j < capped; j += 32) mx = fmaxf(mx, s_e[j * ST + h]);
        for (int j = CAP + lane; j < deg; j += 32) {
            int s = g_csrc[base + j];
            mx = fmaxf(mx, lrelu(ss[s * H + h] + sdv));
        }
#pragma unroll
        for (int o = 16; o; o >>= 1) mx = fmaxf(mx, __shfl_xor_sync(0xffffffffu, mx, o));
        float sm = 0.f;
        for (int j = lane; j < capped; j += 32) sm += expf(s_e[j * ST + h] - mx);
        for (int j = CAP + lane; j < deg; j += 32) {
            int s = g_csrc[base + j];
            sm += expf(lrelu(ss[s * H + h] + sdv) - mx);
        }
#pragma unroll
        for (int o = 16; o; o >>= 1) sm += __shfl_xor_sync(0xffffffffu, sm, o);
        if (lane == 0) { s_m[h] = mx; s_inv[h] = 1.f / (sm + 1e-16f); }
    }
    __syncthreads();

    // Phase C: convert cached logits -> normalized weights in place
    {
        const int jj = (H == 1) ? t : (t >> 2);
        const int h  = (H == 1) ? 0 : (t & 3);
        const float mh = s_m[h], iv = s_inv[h];
        for (int j0 = 0; j0 < capped; j0 += 256 / H) {
            int j = j0 + jj;
            if (j < capped) s_e[j * ST + h] = expf(s_e[j * ST + h] - mh) * iv;
        }
    }
    __syncthreads();

    const int hh = (t * PC) / C;
    float acc[PC];
#pragma unroll
    for (int k = 0; k < PC; k++) acc[k] = 0.f;

    // Phase D: accumulate over cached edges with 2-deep prefetch
    if (PC == 4) {
        const float* fb = feat + t * 4;
        float4 vc = make_float4(0.f, 0.f, 0.f, 0.f), vn = vc;
        if (capped > 0) vc = *(const float4*)(fb + (size_t)s_idx[0] * (H * C));
        if (capped > 1) vn = *(const float4*)(fb + (size_t)s_idx[1] * (H * C));
        for (int j = 0; j < capped; j++) {
            float4 v = vc;
            vc = vn;
            if (j + 2 < capped) vn = *(const float4*)(fb + (size_t)s_idx[j + 2] * (H * C));
            float w = s_e[j * ST + hh];
            acc[0] += v.x * w; acc[1] += v.y * w; acc[2] += v.z * w; acc[3] += v.w * w;
        }
    } else {
        const float* fb = feat + t;
        float vc = 0.f, vn = 0.f;
        if (capped > 0) vc = fb[(size_t)s_idx[0] * C];
        if (capped > 1) vn = fb[(size_t)s_idx[1] * C];
        for (int j = 0; j < capped; j++) {
            float v = vc;
            vc = vn;
            if (j + 2 < capped) vn = fb[(size_t)s_idx[j + 2] * C];
            acc[0] += v * s_e[j * ST];
        }
    }

    // Phase E: overflow edges (deg > CAP) — chunked, reuses s_idx/s_e
    if (deg > CAP) {
        constexpr int CH = 256 / H;
        for (int j0 = CAP; j0 < deg; j0 += CH) {
            __syncthreads();
            const int cnt = min(CH, deg - j0);
            const int jj = (H == 1) ? t : (t >> 2);
            const int h  = (H == 1) ? 0 : (t & 3);
            if (jj < cnt) {
                int s = g_csrc[base + j0 + jj];
                if (h == 0) s_idx[jj] = s;
                s_e[jj * ST + h] =
                    expf(lrelu(ss[s * H + h] + sd[d * H + h]) - s_m[h]) * s_inv[h];
            }
            __syncthreads();
            for (int j = 0; j < cnt; j++) {
                int s = s_idx[j];
                float w = s_e[j * ST + hh];
                if (PC == 4) {
                    float4 v = *(const float4*)&feat[(size_t)s * H * C + t * 4];
                    acc[0] += v.x * w; acc[1] += v.y * w;
                    acc[2] += v.z * w; acc[3] += v.w * w;
                } else {
                    acc[0] += feat[(size_t)s * C + t] * w;
                }
            }
        }
    }

    const int HC = H * C;
#pragma unroll
    for (int k = 0; k < PC; k++) {
        int c = t * PC + k;
        float v = acc[k] + bias[c];
        v = v > 0.f ? v : expm1f(v);
        if (out) out[(size_t)d * HC + c] = v;
        oh[(size_t)d * HC + c] = __float2half_rn(v);
    }
}

// ---------------- graph mean + influence head ----------------
__global__ void k_zero_gf(float* gf) { gf[threadIdx.x] = 0.f; }
__global__ void k_colsum(const float* __restrict__ h, float* __restrict__ gf) {
    float acc = 0.f;
    int t = threadIdx.x;
    for (int r = blockIdx.x; r < NN; r += gridDim.x) acc += h[(size_t)r * F2 + t];
    atomicAdd(&gf[t], acc);
}
__global__ void k_scale_gf(float* gf) { gf[threadIdx.x] *= (1.0f / (float)NN); }

__global__ void k_infl(const float* __restrict__ y, const float* __restrict__ bp1,
                       const float* __restrict__ wp2, const float* __restrict__ bp2,
                       float* __restrict__ infl) {
    int w = (blockIdx.x * blockDim.x + threadIdx.x) >> 5;
    int lane = threadIdx.x & 31;
    if (w >= NN) return;
    float acc = 0.f;
    for (int j = lane; j < PHID; j += 32) {
        float v = y[(size_t)w * PHID + j] + bp1[j];
        v = v > 0.f ? v : 0.f;
        acc += v * wp2[j];
    }
#pragma unroll
    for (int o = 16; o; o >>= 1) acc += __shfl_xor_sync(0xffffffffu, acc, o);
    if (lane == 0) infl[w] = 1.f / (1.f + expf(-(acc + bp2[0])));
}

// ---------------- host: tensor-map builder ----------------
typedef CUresult (*PFN_encodeTiled)(
    CUtensorMap*, CUtensorMapDataType, cuuint32_t, void*,
    const cuuint64_t*, const cuuint64_t*, const cuuint32_t*, const cuuint32_t*,
    CUtensorMapInterleave, CUtensorMapSwizzle, CUtensorMapL2promotion,
    CUtensorMapFloatOOBfill);

static CUtensorMap make_map(PFN_encodeTiled enc, void* base, int K, int rows) {
    CUtensorMap m;
    cuuint64_t dims[2]    = {(cuuint64_t)K, (cuuint64_t)rows};
    cuuint64_t strides[1] = {(cuuint64_t)K * 2};
    cuuint32_t box[2]     = {64, 128};
    cuuint32_t es[2]      = {1, 1};
    enc(&m, CU_TENSOR_MAP_DATA_TYPE_FLOAT16, 2, base, dims, strides, box, es,
        CU_TENSOR_MAP_INTERLEAVE_NONE, CU_TENSOR_MAP_SWIZZLE_128B,
        CU_TENSOR_MAP_L2_PROMOTION_L2_128B, CU_TENSOR_MAP_FLOAT_OOB_FILL_NONE);
    return m;
}

// ---------------- launch ----------------
extern "C" void kernel_launch(void* const* d_in, const int* in_sizes, int n_in,
                              void* d_out, int out_size) {
    const float* x   = (const float*)d_in[0];
    const int*   eidx = (const int*)d_in[1];
    const float* W1  = (const float*)d_in[2];
    const float* as1 = (const float*)d_in[3];
    const float* ad1 = (const float*)d_in[4];
    const float* b1  = (const float*)d_in[5];
    const float* W2  = (const float*)d_in[6];
    const float* as2 = (const float*)d_in[7];
    const float* ad2 = (const float*)d_in[8];
    const float* b2  = (const float*)d_in[9];
    const float* Wp1 = (const float*)d_in[10];
    const float* bp1 = (const float*)d_in[11];
    const float* Wp2 = (const float*)d_in[12];
    const float* bp2 = (const float*)d_in[13];

    const int* src = eidx;
    const int* dst = eidx + EE;

    float* out   = (float*)d_out;
    float* out_h = out;
    float* out_g = out + (size_t)NN * F2;
    float* out_i = out_g + F2;

    float *p_h1, *p_h2, *p_y, *p_ss1, *p_sd1, *p_ss2, *p_sd2;
    __half *p_xh, *p_w1h, *p_o1h, *p_w2h, *p_hh, *p_wph;
    cudaGetSymbolAddress((void**)&p_h1, g_h1);
    cudaGetSymbolAddress((void**)&p_h2, g_h2);
    cudaGetSymbolAddress((void**)&p_y,  g_y);
    cudaGetSymbolAddress((void**)&p_ss1, g_ss1);
    cudaGetSymbolAddress((void**)&p_sd1, g_sd1);
    cudaGetSymbolAddress((void**)&p_ss2, g_ss2);
    cudaGetSymbolAddress((void**)&p_sd2, g_sd2);
    cudaGetSymbolAddress((void**)&p_xh,  g_xh);
    cudaGetSymbolAddress((void**)&p_w1h, g_w1h);
    cudaGetSymbolAddress((void**)&p_o1h, g_o1h);
    cudaGetSymbolAddress((void**)&p_w2h, g_w2h);
    cudaGetSymbolAddress((void**)&p_hh,  g_hh);
    cudaGetSymbolAddress((void**)&p_wph, g_wph);

    PFN_encodeTiled enc = nullptr;
    cudaGetDriverEntryPoint("cuTensorMapEncodeTiled", (void**)&enc, cudaEnableDefault);

    CUtensorMap mA1 = make_map(enc, p_xh,  FIN, NN);
    CUtensorMap mB1 = make_map(enc, p_w1h, FIN, F1);
    CUtensorMap mA2 = make_map(enc, p_o1h, F1,  NN);
    CUtensorMap mB2 = make_map(enc, p_w2h, F1,  F2);
    CUtensorMap mA3 = make_map(enc, p_hh,  F2,  NN);
    CUtensorMap mB3 = make_map(enc, p_wph, F2, PHID);

    cudaFuncSetAttribute(hgemm_tma, cudaFuncAttributeMaxDynamicSharedMemorySize, TG_SMEM);

    // side stream + events (created once, outside capture on the correctness call)
    static cudaStream_t s1 = nullptr;
    static cudaEvent_t evF1 = nullptr, evJ1 = nullptr, evF2 = nullptr, evJ2 = nullptr;
    if (!s1) {
        cudaStreamCreateWithFlags(&s1, cudaStreamNonBlocking);
        cudaEventCreateWithFlags(&evF1, cudaEventDisableTiming);
        cudaEventCreateWithFlags(&evJ1, cudaEventDisableTiming);
        cudaEventCreateWithFlags(&evF2, cudaEventDisableTiming);
        cudaEventCreateWithFlags(&evJ2, cudaEventDisableTiming);
    }

    const int MR = (NN + 127) / 128;  // 157 row tiles

    // ---- fork 1: CSR build + later-weight casts run beside GEMM1 path ----
    cudaEventRecord(evF1, 0);
    cudaStreamWaitEvent(s1, evF1, 0);
    k_castT<<<(F1 * F2 + 255) / 256, 256, 0, s1>>>(W2, p_w2h, F1, F2);
    k_castT<<<(F2 * PHID + 255) / 256, 256, 0, s1>>>(Wp1, p_wph, F2, PHID);
    k_deg_init <<<(NN + 255) / 256, 256, 0, s1>>>(NN);
    k_deg_count<<<(EE + 255) / 256, 256, 0, s1>>>(dst, EE);
    k_scan<<<1, 1024, 0, s1>>>(NN);
    k_fill<<<(ETOT + 255) / 256, 256, 0, s1>>>(src, dst, EE, NN);
    cudaEventRecord(evJ1, s1);

    // ---- main: casts -> GEMM1 -> slogits1 ----
    k_cast <<<(NN * FIN + 255) / 256, 256>>>(x, p_xh, NN * FIN);
    k_castT<<<(FIN * F1 + 255) / 256, 256>>>(W1, p_w1h, FIN, F1);
    hgemm_tma<<<dim3(F1 / 128, MR), 256, TG_SMEM>>>(mA1, mB1, p_h1, NN, F1, FIN);
    k_slogits<<<(NN * HH1 * 32 + 255) / 256, 256>>>(p_h1, as1, ad1, p_ss1, p_sd1, NN, HH1, HD);

    cudaStreamWaitEvent(0, evJ1, 0);

    // layer 1 softmax-aggregate + bias + ELU -> fp16 plane (GEMM2 A)
    k_agg<HH1, HD, 4><<<NN, 256>>>(p_h1, p_ss1, p_sd1, b1, nullptr, p_o1h);

    // GEMM2: h2 = o1 @ W2
    hgemm_tma<<<dim3(F2 / 128, MR), 256, TG_SMEM>>>(mA2, mB2, p_h2, NN, F2, F1);

    // attention logits layer 2
    k_slogits<<<(NN * 32 + 255) / 256, 256>>>(p_h2, as2, ad2, p_ss2, p_sd2, NN, 1, HD);

    // layer 2 softmax-aggregate -> fp32 out_h + fp16 plane (GEMM3 A)
    k_agg<1, F2, 1><<<NN, 256>>>(p_h2, p_ss2, p_sd2, b2, out_h, p_hh);

    // ---- fork 2: graph mean beside influence head ----
    cudaEventRecord(evF2, 0);
    cudaStreamWaitEvent(s1, evF2, 0);
    k_zero_gf<<<1, F2, 0, s1>>>(out_g);
    k_colsum<<<160, F2, 0, s1>>>(out_h, out_g);
    k_scale_gf<<<1, F2, 0, s1>>>(out_g);
    cudaEventRecord(evJ2, s1);

    // main: influence head
    hgemm_tma<<<dim3(PHID / 128, MR), 256, TG_SMEM>>>(mA3, mB3, p_y, NN, PHID, F2);
    k_infl<<<(NN * 32 + 255) / 256, 256>>>(p_y, bp1, Wp2, bp2, out_i);

    cudaStreamWaitEvent(0, evJ2, 0);
}

// round 9
// speedup vs baseline: 1.1225x; 1.0452x over previous
#include <cuda_runtime.h>
#include <cuda.h>
#include <cuda_fp16.h>
#include <math.h>
#include <cstdint>

#define NN   20000
#define EE   320000
#define ETOT 340000
#define FIN  384
#define F1   1024
#define HH1  4
#define HD   256
#define F2   256
#define PHID 128
#define NSPLIT 10112          // 79 row tiles of 128
#define TLO 79
#define THI 78                // ceil(20000/128)=157 total tiles

// ---------------- scratch (static device globals; no runtime alloc) ----------
__device__ float g_h1[(size_t)NN * F1];
__device__ float g_h2[(size_t)NN * F2];
__device__ float g_y [(size_t)NN * PHID];
__device__ float g_ss1[NN * HH1];
__device__ float g_sd1[NN * HH1];
__device__ float g_ss2[NN];
__device__ float g_sd2[NN];
__device__ int   g_deg[NN];
__device__ int   g_off[NN + 1];
__device__ int   g_cur[NN];
__device__ int   g_csrc[ETOT];
// fp16 operand planes (A row-major [M,K]; B transposed [N,K])
__device__ __align__(128) __half g_xh [(size_t)NN * FIN];
__device__ __align__(128) __half g_w1h[(size_t)F1 * FIN];
__device__ __align__(128) __half g_o1h[(size_t)NN * F1];
__device__ __align__(128) __half g_w2h[(size_t)F2 * F1];
__device__ __align__(128) __half g_hh [(size_t)NN * F2];
__device__ __align__(128) __half g_wph[(size_t)PHID * F2];

// ---------------- helpers ----------------
__device__ __forceinline__ uint32_t smem_u32(const void* p) {
    uint32_t a;
    asm("{ .reg .u64 t; cvta.to.shared.u64 t, %1; cvt.u32.u64 %0, t; }" : "=r"(a) : "l"(p));
    return a;
}
__device__ __forceinline__ void ldm4(uint32_t* r, uint32_t a) {
    asm volatile("ldmatrix.sync.aligned.m8n8.x4.shared.b16 {%0,%1,%2,%3}, [%4];"
                 : "=r"(r[0]), "=r"(r[1]), "=r"(r[2]), "=r"(r[3]) : "r"(a));
}
__device__ __forceinline__ void mma16816(float* c, const uint32_t* a, uint32_t b0, uint32_t b1) {
    asm volatile("mma.sync.aligned.m16n8k16.row.col.f32.f16.f16.f32 "
                 "{%0,%1,%2,%3}, {%4,%5,%6,%7}, {%8,%9}, {%0,%1,%2,%3};"
                 : "+f"(c[0]), "+f"(c[1]), "+f"(c[2]), "+f"(c[3])
                 : "r"(a[0]), "r"(a[1]), "r"(a[2]), "r"(a[3]), "r"(b0), "r"(b1));
}
#define MBARRIER_INIT(mb, c) \
    asm volatile("mbarrier.init.shared.b64 [%0], %1;" :: "r"((uint32_t)(mb)), "r"((uint32_t)(c)) : "memory")
#define MBARRIER_EXPECT_TX(mb, b) \
    asm volatile("mbarrier.arrive.expect_tx.shared.b64 _, [%0], %1;" \
                 :: "r"((uint32_t)(mb)), "r"((uint32_t)(b)) : "memory")
#define MBARRIER_WAIT_PARITY(mb, par) do { \
    uint32_t _m = (uint32_t)(mb), _p = (uint32_t)(par), _d; \
    asm volatile("{\n\t.reg .pred p;\n\t" \
        "mbarrier.try_wait.parity.acquire.cta.shared::cta.b64 p, [%1], %2;\n\t" \
        "selp.b32 %0, 1, 0, p;\n\t}" : "=r"(_d) : "r"(_m), "r"(_p) : "memory"); \
    if (!_d) { \
        asm volatile("{\n\t.reg .pred P1;\n\tWL_%=:\n\t" \
            "mbarrier.try_wait.parity.acquire.cta.shared::cta.b64 P1, [%0], %1, 0x989680;\n\t" \
            "@P1 bra.uni WD_%=;\n\tbra.uni WL_%=;\n\tWD_%=:\n\t}" \
            :: "r"(_m), "r"(_p) : "memory"); \
    } } while (0)
__device__ __forceinline__ void tma2d(uint32_t dst, const void* map, int x, int y, uint32_t mb) {
    asm volatile(
        "cp.async.bulk.tensor.2d.shared::cta.global.tile.mbarrier::complete_tx::bytes "
        "[%0], [%1, {%2, %3}], [%4];"
        :: "r"(dst), "l"(map), "r"(x), "r"(y), "r"(mb) : "memory");
}
#define SW128(o) ((o) ^ (((o) >> 3) & 0x70u))

// ---------------- fp16 cast kernels ----------------
__global__ void k_cast(const float* __restrict__ in, __half* __restrict__ o, int total) {
    int i = blockIdx.x * blockDim.x + threadIdx.x;
    if (i < total) o[i] = __float2half_rn(in[i]);
}
__global__ void k_castT(const float* __restrict__ W, __half* __restrict__ o, int K, int N) {
    int i = blockIdx.x * blockDim.x + threadIdx.x;
    if (i >= K * N) return;
    int k = i / N, n = i % N;
    o[(size_t)n * K + k] = __float2half_rn(W[i]);
}

// ============== TMA HMMA GEMM: C[M,N] = A[M,K] @ B[N,K]^T ====================
// fp16 in, fp32 accum/out. CTA 128x128, BK=64 (SW128), 3-stage TMA pipeline,
// 8 warps (32x64 each), 2 CTAs/SM. ytile0 = row-tile offset for split launches.
#define TG_STAGE 32768
#define TG_SMEM (1024 + 3 * TG_STAGE)

__global__ void __launch_bounds__(256, 2)
hgemm_tma(const __grid_constant__ CUtensorMap mA,
          const __grid_constant__ CUtensorMap mB,
          float* __restrict__ C, int M, int N, int K, int ytile0) {
    extern __shared__ unsigned char smraw[];
    const uint32_t base0 = (smem_u32(smraw) + 1023u) & ~1023u;
    const uint32_t mbb = base0;
    const uint32_t tile0 = base0 + 1024;
    const int tid = threadIdx.x, wid = tid >> 5, lane = tid & 31;
    const int bm = (blockIdx.y + ytile0) * 128, bn = blockIdx.x * 128;
    const int wr = (wid >> 1) * 32, wn = (wid & 1) * 64;
    const int nc = K >> 6;

    if (tid == 0) {
        MBARRIER_INIT(mbb + 0, 1);
        MBARRIER_INIT(mbb + 8, 1);
        MBARRIER_INIT(mbb + 16, 1);
    }
    __syncthreads();

    if (tid == 0) {
#pragma unroll
        for (int s = 0; s < 2; s++) {
            uint32_t mb = mbb + 8u * s;
            uint32_t t = tile0 + (uint32_t)s * TG_STAGE;
            MBARRIER_EXPECT_TX(mb, TG_STAGE);
            tma2d(t,          &mA, s * 64, bm, mb);
            tma2d(t + 16384u, &mB, s * 64, bn, mb);
        }
    }

    float acc[2][8][4];
#pragma unroll
    for (int a = 0; a < 2; a++)
#pragma unroll
        for (int b = 0; b < 8; b++)
#pragma unroll
            for (int c = 0; c < 4; c++) acc[a][b][c] = 0.f;

    for (int i = 0; i < nc; i++) {
        const int b = i % 3;
        MBARRIER_WAIT_PARITY(mbb + 8u * b, (i / 3) & 1);
        __syncthreads();
        if (tid == 0 && i + 2 < nc) {
            const int nb = (i + 2) % 3;
            uint32_t mb = mbb + 8u * nb;
            uint32_t t = tile0 + (uint32_t)nb * TG_STAGE;
            MBARRIER_EXPECT_TX(mb, TG_STAGE);
            tma2d(t,          &mA, (i + 2) * 64, bm, mb);
            tma2d(t + 16384u, &mB, (i + 2) * 64, bn, mb);
        }

        const uint32_t tA = tile0 + (uint32_t)b * TG_STAGE;
        const uint32_t tB = tA + 16384u;
        const int gq = lane >> 3;
#pragma unroll
        for (int ks = 0; ks < 4; ks++) {
            uint32_t ar[2][4], br[4][4];
#pragma unroll
            for (int mt = 0; mt < 2; mt++) {
                uint32_t lin = (uint32_t)(wr + mt * 16 + (lane & 15)) * 128u
                             + (uint32_t)(ks * 32 + (lane >> 4) * 16);
                ldm4(ar[mt], tA + SW128(lin));
            }
#pragma unroll
            for (int bt = 0; bt < 4; bt++) {
                uint32_t lin = (uint32_t)(wn + bt * 16 + ((gq >> 1) << 3) + (lane & 7)) * 128u
                             + (uint32_t)(ks * 32 + (gq & 1) * 16);
                ldm4(br[bt], tB + SW128(lin));
            }
#pragma unroll
            for (int mt = 0; mt < 2; mt++)
#pragma unroll
                for (int j = 0; j < 8; j++) {
                    const int bt = j >> 1, p0 = (j & 1) * 2;
                    mma16816(acc[mt][j], ar[mt], br[bt][p0], br[bt][p0 + 1]);
                }
        }
    }

#pragma unroll
    for (int mt = 0; mt < 2; mt++) {
        int m0 = bm + wr + mt * 16 + (lane >> 2);
#pragma unroll
        for (int j = 0; j < 8; j++) {
            int n0 = bn + wn + j * 8 + (lane & 3) * 2;
            if (m0 < M)
                *(float2*)&C[(size_t)m0 * N + n0] = make_float2(acc[mt][j][0], acc[mt][j][1]);
            if (m0 + 8 < M)
                *(float2*)&C[(size_t)(m0 + 8) * N + n0] = make_float2(acc[mt][j][2], acc[mt][j][3]);
        }
    }
}

// ---------------- attention logits (fp32 feat) ----------------
__global__ void k_slogits(const float* __restrict__ feat, const float* __restrict__ asrc,
                          const float* __restrict__ adst, float* __restrict__ ss,
                          float* __restrict__ sd, int n, int H, int C) {
    int w = (blockIdx.x * blockDim.x + threadIdx.x) >> 5;
    int lane = threadIdx.x & 31;
    if (w >= n * H) return;
    int node = w / H, h = w % H;
    const float* row = &feat[(size_t)node * H * C + h * C];
    float a = 0.f, b = 0.f;
    for (int c = lane; c < C; c += 32) {
        float v = row[c];
        a += v * asrc[h * C + c];
        b += v * adst[h * C + c];
    }
#pragma unroll
    for (int o = 16; o; o >>= 1) {
        a += __shfl_xor_sync(0xffffffffu, a, o);
        b += __shfl_xor_sync(0xffffffffu, b, o);
    }
    if (lane == 0) { ss[w] = a; sd[w] = b; }
}

// ---------------- CSR build ----------------
__global__ void k_deg_init(int n) {
    int i = blockIdx.x * blockDim.x + threadIdx.x;
    if (i < n) g_deg[i] = 1;
}
__global__ void k_deg_count(const int* __restrict__ dst, int e) {
    int i = blockIdx.x * blockDim.x + threadIdx.x;
    if (i < e) atomicAdd(&g_deg[dst[i]], 1);
}
__global__ void k_scan(int n) {
    __shared__ int sums[1024];
    int tid = threadIdx.x;
    int chunk = (n + 1023) / 1024;
    int lo = tid * chunk, hi = min(lo + chunk, n);
    int s = 0;
    for (int i = lo; i < hi; i++) s += g_deg[i];
    sums[tid] = s;
    __syncthreads();
    for (int d = 1; d < 1024; d <<= 1) {
        int v = (tid >= d) ? sums[tid - d] : 0;
        __syncthreads();
        sums[tid] += v;
        __syncthreads();
    }
    int base = (tid == 0) ? 0 : sums[tid - 1];
    for (int i = lo; i < hi; i++) {
        g_off[i] = base;
        g_cur[i] = base;
        base += g_deg[i];
    }
    if (tid == 1023) g_off[n] = sums[1023];
}
__global__ void k_fill(const int* __restrict__ src, const int* __restrict__ dst, int e, int n) {
    int i = blockIdx.x * blockDim.x + threadIdx.x;
    if (i >= e + n) return;
    int s, d;
    if (i < e) { s = src[i]; d = dst[i]; }
    else       { s = i - e;  d = i - e; }
    int pos = atomicAdd(&g_cur[d], 1);
    g_csrc[pos] = s;
}

// ---------------- per-dst softmax + aggregation + bias + ELU ----------------
__device__ __forceinline__ float lrelu(float x) { return x > 0.f ? x : 0.2f * x; }

template <int H, int C, int PC>   // PC = H*C/256
__global__ void __launch_bounds__(256)
k_agg(const float* __restrict__ feat, const float* __restrict__ ss,
      const float* __restrict__ sd, const float* __restrict__ bias,
      float* __restrict__ out, __half* __restrict__ oh, int d0) {
    constexpr int CAP = 256;
    constexpr int ST  = (H == 4) ? 5 : 1;
    const int d = blockIdx.x + d0;
    const int base = g_off[d], deg = g_off[d + 1] - base;
    const int capped = min(deg, CAP);
    __shared__ float s_m[H], s_inv[H];
    __shared__ float s_e[CAP * ST];
    __shared__ int   s_idx[CAP];
    const int t = threadIdx.x, wid = t >> 5, lane = t & 31;

    // Phase A: cache src indices + raw leaky-relu logits (one gather pass)
    {
        const int jj = (H == 1) ? t : (t >> 2);
        const int h  = (H == 1) ? 0 : (t & 3);
        const float sdv = sd[d * H + h];
        for (int j0 = 0; j0 < capped; j0 += 256 / H) {
            int j = j0 + jj;
            if (j < capped) {
                int s = g_csrc[base + j];
                if (h == 0) s_idx[j] = s;
                s_e[j * ST + h] = lrelu(ss[s * H + h] + sdv);
            }
        }
    }
    __syncthreads();

    // Phase B: per-head max + denominator
    if (wid < H) {
        const int h = wid;
        const float sdv = sd[d * H + h];
        float mx = -1e30f;
        for (int j = lane; j < capped; j += 32) mx = fmaxf(mx, s_e[j * ST + h]);
        for (int j = CAP + lane; j < deg; j += 32) {
            int s = g_csrc[base + j];
            mx = fmaxf(mx, lrelu(ss[s * H + h] + sdv));
        }
#pragma unroll
        for (int o = 16; o; o >>= 1) mx = fmaxf(mx, __shfl_xor_sync(0xffffffffu, mx, o));
        float sm = 0.f;
        for (int j = lane; j < capped; j += 32) sm += expf(s_e[j * ST + h] - mx);
        for (int j = CAP + lane; j < deg; j += 32) {
            int s = g_csrc[base + j];
            sm += expf(lrelu(ss[s * H + h] + sdv) - mx);
        }
#pragma unroll
        for (int o = 16; o; o >>= 1) sm += __shfl_xor_sync(0xffffffffu, sm, o);
        if (lane == 0) { s_m[h] = mx; s_inv[h] = 1.f / (sm + 1e-16f); }
    }
    __syncthreads();

    // Phase C: logits -> normalized weights in place
    {
        const int jj = (H == 1) ? t : (t >> 2);
        const int h  = (H == 1) ? 0 : (t & 3);
        const float mh = s_m[h], iv = s_inv[h];
        for (int j0 = 0; j0 < capped; j0 += 256 / H) {
            int j = j0 + jj;
            if (j < capped) s_e[j * ST + h] = expf(s_e[j * ST + h] - mh) * iv;
        }
    }
    __syncthreads();

    const int hh = (t * PC) / C;
    float acc[PC];
#pragma unroll
    for (int k = 0; k < PC; k++) acc[k] = 0.f;

    // Phase D: accumulate with deep prefetch (4-wide float4 / 8-wide scalar)
    if (PC == 4) {
        const float* fb = feat + t * 4;
        const int RW = H * C;
        float4 b0 = make_float4(0, 0, 0, 0), b1 = b0, b2 = b0, b3 = b0;
        if (capped > 0) b0 = *(const float4*)(fb + (size_t)s_idx[0] * RW);
        if (capped > 1) b1 = *(const float4*)(fb + (size_t)s_idx[1] * RW);
        if (capped > 2) b2 = *(const float4*)(fb + (size_t)s_idx[2] * RW);
        if (capped > 3) b3 = *(const float4*)(fb + (size_t)s_idx[3] * RW);
        int j = 0;
        for (; j + 4 <= capped; j += 4) {
            float w0 = s_e[(j + 0) * ST + hh], w1 = s_e[(j + 1) * ST + hh];
            float w2 = s_e[(j + 2) * ST + hh], w3 = s_e[(j + 3) * ST + hh];
            float4 v0 = b0, v1 = b1, v2 = b2, v3 = b3;
            if (j + 4 < capped) b0 = *(const float4*)(fb + (size_t)s_idx[j + 4] * RW);
            if (j + 5 < capped) b1 = *(const float4*)(fb + (size_t)s_idx[j + 5] * RW);
            if (j + 6 < capped) b2 = *(const float4*)(fb + (size_t)s_idx[j + 6] * RW);
            if (j + 7 < capped) b3 = *(const float4*)(fb + (size_t)s_idx[j + 7] * RW);
            acc[0] += v0.x * w0 + v1.x * w1 + v2.x * w2 + v3.x * w3;
            acc[1] += v0.y * w0 + v1.y * w1 + v2.y * w2 + v3.y * w3;
            acc[2] += v0.z * w0 + v1.z * w1 + v2.z * w2 + v3.z * w3;
            acc[3] += v0.w * w0 + v1.w * w1 + v2.w * w2 + v3.w * w3;
        }
        if (j < capped) {
            float w = s_e[j * ST + hh];
            acc[0] += b0.x * w; acc[1] += b0.y * w; acc[2] += b0.z * w; acc[3] += b0.w * w;
        }
        if (j + 1 < capped) {
            float w = s_e[(j + 1) * ST + hh];
            acc[0] += b1.x * w; acc[1] += b1.y * w; acc[2] += b1.z * w; acc[3] += b1.w * w;
        }
        if (j + 2 < capped) {
            float w = s_e[(j + 2) * ST + hh];
            acc[0] += b2.x * w; acc[1] += b2.y * w; acc[2] += b2.z * w; acc[3] += b2.w * w;
        }
    } else {
        const float* fb = feat + t;
        float c0 = 0, c1 = 0, c2 = 0, c3 = 0, c4 = 0, c5 = 0, c6 = 0, c7 = 0;
        if (capped > 0) c0 = fb[(size_t)s_idx[0] * C];
        if (capped > 1) c1 = fb[(size_t)s_idx[1] * C];
        if (capped > 2) c2 = fb[(size_t)s_idx[2] * C];
        if (capped > 3) c3 = fb[(size_t)s_idx[3] * C];
        if (capped > 4) c4 = fb[(size_t)s_idx[4] * C];
        if (capped > 5) c5 = fb[(size_t)s_idx[5] * C];
        if (capped > 6) c6 = fb[(size_t)s_idx[6] * C];
        if (capped > 7) c7 = fb[(size_t)s_idx[7] * C];
        int j = 0;
        for (; j + 8 <= capped; j += 8) {
            float a0 = c0 * s_e[j + 0] + c1 * s_e[j + 1] + c2 * s_e[j + 2] + c3 * s_e[j + 3];
            float a1 = c4 * s_e[j + 4] + c5 * s_e[j + 5] + c6 * s_e[j + 6] + c7 * s_e[j + 7];
            if (j +  8 < capped) c0 = fb[(size_t)s_idx[j +  8] * C];
            if (j +  9 < capped) c1 = fb[(size_t)s_idx[j +  9] * C];
            if (j + 10 < capped) c2 = fb[(size_t)s_idx[j + 10] * C];
            if (j + 11 < capped) c3 = fb[(size_t)s_idx[j + 11] * C];
            if (j + 12 < capped) c4 = fb[(size_t)s_idx[j + 12] * C];
            if (j + 13 < capped) c5 = fb[(size_t)s_idx[j + 13] * C];
            if (j + 14 < capped) c6 = fb[(size_t)s_idx[j + 14] * C];
            if (j + 15 < capped) c7 = fb[(size_t)s_idx[j + 15] * C];
            acc[0] += a0 + a1;
        }
        if (j     < capped) acc[0] += c0 * s_e[j];
        if (j + 1 < capped) acc[0] += c1 * s_e[j + 1];
        if (j + 2 < capped) acc[0] += c2 * s_e[j + 2];
        if (j + 3 < capped) acc[0] += c3 * s_e[j + 3];
        if (j + 4 < capped) acc[0] += c4 * s_e[j + 4];
        if (j + 5 < capped) acc[0] += c5 * s_e[j + 5];
        if (j + 6 < capped) acc[0] += c6 * s_e[j + 6];
    }

    // Phase E: overflow edges (deg > CAP)
    if (deg > CAP) {
        constexpr int CH = 256 / H;
        for (int j0 = CAP; j0 < deg; j0 += CH) {
            __syncthreads();
            const int cnt = min(CH, deg - j0);
            const int jj = (H == 1) ? t : (t >> 2);
            const int h  = (H == 1) ? 0 : (t & 3);
            if (jj < cnt) {
                int s = g_csrc[base + j0 + jj];
                if (h == 0) s_idx[jj] = s;
                s_e[jj * ST + h] =
                    expf(lrelu(ss[s * H + h] + sd[d * H + h]) - s_m[h]) * s_inv[h];
            }
            __syncthreads();
            for (int j = 0; j < cnt; j++) {
                int s = s_idx[j];
                float w = s_e[j * ST + hh];
                if (PC == 4) {
                    float4 v = *(const float4*)&feat[(size_t)s * H * C + t * 4];
                    acc[0] += v.x * w; acc[1] += v.y * w;
                    acc[2] += v.z * w; acc[3] += v.w * w;
                } else {
                    acc[0] += feat[(size_t)s * C + t] * w;
                }
            }
        }
    }

    const int HC = H * C;
#pragma unroll
    for (int k = 0; k < PC; k++) {
        int c = t * PC + k;
        float v = acc[k] + bias[c];
        v = v > 0.f ? v : expm1f(v);
        if (out) out[(size_t)d * HC + c] = v;
        oh[(size_t)d * HC + c] = __float2half_rn(v);
    }
}

// ---------------- graph mean + influence head ----------------
__global__ void k_zero_gf(float* gf) { gf[threadIdx.x] = 0.f; }
__global__ void k_colsum(const float* __restrict__ h, float* __restrict__ gf) {
    float acc = 0.f;
    int t = threadIdx.x;
    for (int r = blockIdx.x; r < NN; r += gridDim.x) acc += h[(size_t)r * F2 + t];
    atomicAdd(&gf[t], acc);
}
__global__ void k_scale_gf(float* gf) { gf[threadIdx.x] *= (1.0f / (float)NN); }

__global__ void k_infl(const float* __restrict__ y, const float* __restrict__ bp1,
                       const float* __restrict__ wp2, const float* __restrict__ bp2,
                       float* __restrict__ infl, int n) {
    int w = (blockIdx.x * blockDim.x + threadIdx.x) >> 5;
    int lane = threadIdx.x & 31;
    if (w >= n) return;
    float acc = 0.f;
    for (int j = lane; j < PHID; j += 32) {
        float v = y[(size_t)w * PHID + j] + bp1[j];
        v = v > 0.f ? v : 0.f;
        acc += v * wp2[j];
    }
#pragma unroll
    for (int o = 16; o; o >>= 1) acc += __shfl_xor_sync(0xffffffffu, acc, o);
    if (lane == 0) infl[w] = 1.f / (1.f + expf(-(acc + bp2[0])));
}

// ---------------- host: tensor-map builder ----------------
typedef CUresult (*PFN_encodeTiled)(
    CUtensorMap*, CUtensorMapDataType, cuuint32_t, void*,
    const cuuint64_t*, const cuuint64_t*, const cuuint32_t*, const cuuint32_t*,
    CUtensorMapInterleave, CUtensorMapSwizzle, CUtensorMapL2promotion,
    CUtensorMapFloatOOBfill);

static CUtensorMap make_map(PFN_encodeTiled enc, void* base, int K, int rows) {
    CUtensorMap m;
    cuuint64_t dims[2]    = {(cuuint64_t)K, (cuuint64_t)rows};
    cuuint64_t strides[1] = {(cuuint64_t)K * 2};
    cuuint32_t box[2]     = {64, 128};
    cuuint32_t es[2]      = {1, 1};
    enc(&m, CU_TENSOR_MAP_DATA_TYPE_FLOAT16, 2, base, dims, strides, box, es,
        CU_TENSOR_MAP_INTERLEAVE_NONE, CU_TENSOR_MAP_SWIZZLE_128B,
        CU_TENSOR_MAP_L2_PROMOTION_L2_128B, CU_TENSOR_MAP_FLOAT_OOB_FILL_NONE);
    return m;
}

// ---------------- launch ----------------
extern "C" void kernel_launch(void* const* d_in, const int* in_sizes, int n_in,
                              void* d_out, int out_size) {
    const float* x   = (const float*)d_in[0];
    const int*   eidx = (const int*)d_in[1];
    const float* W1  = (const float*)d_in[2];
    const float* as1 = (const float*)d_in[3];
    const float* ad1 = (const float*)d_in[4];
    const float* b1  = (const float*)d_in[5];
    const float* W2  = (const float*)d_in[6];
    const float* as2 = (const float*)d_in[7];
    const float* ad2 = (const float*)d_in[8];
    const float* b2  = (const float*)d_in[9];
    const float* Wp1 = (const float*)d_in[10];
    const float* bp1 = (const float*)d_in[11];
    const float* Wp2 = (const float*)d_in[12];
    const float* bp2 = (const float*)d_in[13];

    const int* src = eidx;
    const int* dst = eidx + EE;

    float* out   = (float*)d_out;
    float* out_h = out;
    float* out_g = out + (size_t)NN * F2;
    float* out_i = out_g + F2;

    float *p_h1, *p_h2, *p_y, *p_ss1, *p_sd1, *p_ss2, *p_sd2;
    __half *p_xh, *p_w1h, *p_o1h, *p_w2h, *p_hh, *p_wph;
    cudaGetSymbolAddress((void**)&p_h1, g_h1);
    cudaGetSymbolAddress((void**)&p_h2, g_h2);
    cudaGetSymbolAddress((void**)&p_y,  g_y);
    cudaGetSymbolAddress((void**)&p_ss1, g_ss1);
    cudaGetSymbolAddress((void**)&p_sd1, g_sd1);
    cudaGetSymbolAddress((void**)&p_ss2, g_ss2);
    cudaGetSymbolAddress((void**)&p_sd2, g_sd2);
    cudaGetSymbolAddress((void**)&p_xh,  g_xh);
    cudaGetSymbolAddress((void**)&p_w1h, g_w1h);
    cudaGetSymbolAddress((void**)&p_o1h, g_o1h);
    cudaGetSymbolAddress((void**)&p_w2h, g_w2h);
    cudaGetSymbolAddress((void**)&p_hh,  g_hh);
    cudaGetSymbolAddress((void**)&p_wph, g_wph);

    PFN_encodeTiled enc = nullptr;
    cudaGetDriverEntryPoint("cuTensorMapEncodeTiled", (void**)&enc, cudaEnableDefault);

    CUtensorMap mA1 = make_map(enc, p_xh,  FIN, NN);
    CUtensorMap mB1 = make_map(enc, p_w1h, FIN, F1);
    CUtensorMap mA2 = make_map(enc, p_o1h, F1,  NN);
    CUtensorMap mB2 = make_map(enc, p_w2h, F1,  F2);
    CUtensorMap mA3 = make_map(enc, p_hh,  F2,  NN);
    CUtensorMap mB3 = make_map(enc, p_wph, F2, PHID);

    cudaFuncSetAttribute(hgemm_tma, cudaFuncAttributeMaxDynamicSharedMemorySize, TG_SMEM);

    static cudaStream_t s1 = nullptr;
    static cudaEvent_t evF1 = nullptr, evJ1 = nullptr, evA1lo = nullptr,
                       evS1a = nullptr, evA2lo = nullptr, evA2hi = nullptr,
                       evJ2 = nullptr;
    if (!s1) {
        cudaStreamCreateWithFlags(&s1, cudaStreamNonBlocking);
        cudaEventCreateWithFlags(&evF1,  cudaEventDisableTiming);
        cudaEventCreateWithFlags(&evJ1,  cudaEventDisableTiming);
        cudaEventCreateWithFlags(&evA1lo, cudaEventDisableTiming);
        cudaEventCreateWithFlags(&evS1a, cudaEventDisableTiming);
        cudaEventCreateWithFlags(&evA2lo, cudaEventDisableTiming);
        cudaEventCreateWithFlags(&evA2hi, cudaEventDisableTiming);
        cudaEventCreateWithFlags(&evJ2,  cudaEventDisableTiming);
    }

    // ---- fork 1: CSR build + later-weight casts beside GEMM1 path ----
    cudaEventRecord(evF1, 0);
    cudaStreamWaitEvent(s1, evF1, 0);
    k_castT<<<(F1 * F2 + 255) / 256, 256, 0, s1>>>(W2, p_w2h, F1, F2);
    k_castT<<<(F2 * PHID + 255) / 256, 256, 0, s1>>>(Wp1, p_wph, F2, PHID);
    k_deg_init <<<(NN + 255) / 256, 256, 0, s1>>>(NN);
    k_deg_count<<<(EE + 255) / 256, 256, 0, s1>>>(dst, EE);
    k_scan<<<1, 1024, 0, s1>>>(NN);
    k_fill<<<(ETOT + 255) / 256, 256, 0, s1>>>(src, dst, EE, NN);
    cudaEventRecord(evJ1, s1);

    // ---- main: casts -> GEMM1 -> slogits1 ----
    k_cast <<<(NN * FIN + 255) / 256, 256>>>(x, p_xh, NN * FIN);
    k_castT<<<(FIN * F1 + 255) / 256, 256>>>(W1, p_w1h, FIN, F1);
    hgemm_tma<<<dim3(F1 / 128, TLO + THI), 256, TG_SMEM>>>(mA1, mB1, p_h1, NN, F1, FIN, 0);
    k_slogits<<<(NN * HH1 * 32 + 255) / 256, 256>>>(p_h1, as1, ad1, p_ss1, p_sd1, NN, HH1, HD);

    cudaStreamWaitEvent(0, evJ1, 0);

    // ---- agg1 split-pipeline with GEMM2 + slogits2 ----
    k_agg<HH1, HD, 4><<<NSPLIT, 256>>>(p_h1, p_ss1, p_sd1, b1, nullptr, p_o1h, 0);
    cudaEventRecord(evA1lo, 0);
    cudaStreamWaitEvent(s1, evA1lo, 0);
    hgemm_tma<<<dim3(F2 / 128, TLO), 256, TG_SMEM, s1>>>(mA2, mB2, p_h2, NN, F2, F1, 0);
    k_slogits<<<(NSPLIT * 32 + 255) / 256, 256, 0, s1>>>(p_h2, as2, ad2, p_ss2, p_sd2,
                                                         NSPLIT, 1, HD);
    cudaEventRecord(evS1a, s1);

    k_agg<HH1, HD, 4><<<NN - NSPLIT, 256>>>(p_h1, p_ss1, p_sd1, b1, nullptr, p_o1h, NSPLIT);
    hgemm_tma<<<dim3(F2 / 128, THI), 256, TG_SMEM>>>(mA2, mB2, p_h2, NN, F2, F1, TLO);
    k_slogits<<<((NN - NSPLIT) * 32 + 255) / 256, 256>>>(p_h2 + (size_t)NSPLIT * F2, as2, ad2,
                                                         p_ss2 + NSPLIT, p_sd2 + NSPLIT,
                                                         NN - NSPLIT, 1, HD);
    cudaStreamWaitEvent(0, evS1a, 0);

    // ---- agg2 split-pipeline with GEMM3 + infl ----
    k_agg<1, F2, 1><<<NSPLIT, 256>>>(p_h2, p_ss2, p_sd2, b2, out_h, p_hh, 0);
    cudaEventRecord(evA2lo, 0);
    cudaStreamWaitEvent(s1, evA2lo, 0);
    hgemm_tma<<<dim3(PHID / 128, TLO), 256, TG_SMEM, s1>>>(mA3, mB3, p_y, NN, PHID, F2, 0);
    k_infl<<<(NSPLIT * 32 + 255) / 256, 256, 0, s1>>>(p_y, bp1, Wp2, bp2, out_i, NSPLIT);

    k_agg<1, F2, 1><<<NN - NSPLIT, 256>>>(p_h2, p_ss2, p_sd2, b2, out_h, p_hh, NSPLIT);
    cudaEventRecord(evA2hi, 0);

    // side: graph mean (needs full out_h)
    cudaStreamWaitEvent(s1, evA2hi, 0);
    k_zero_gf<<<1, F2, 0, s1>>>(out_g);
    k_colsum<<<160, F2, 0, s1>>>(out_h, out_g);
    k_scale_gf<<<1, F2, 0, s1>>>(out_g);
    cudaEventRecord(evJ2, s1);

    // main: GEMM3_hi + infl_hi
    hgemm_tma<<<dim3(PHID / 128, THI), 256, TG_SMEM>>>(mA3, mB3, p_y, NN, PHID, F2, TLO);
    k_infl<<<((NN - NSPLIT) * 32 + 255) / 256, 256>>>(p_y + (size_t)NSPLIT * PHID, bp1, Wp2, bp2,
                                                      out_i + NSPLIT, NN - NSPLIT);
    cudaStreamWaitEvent(0, evJ2, 0);
}

// round 10
// speedup vs baseline: 1.2056x; 1.0740x over previous
#include <cuda_runtime.h>
#include <cuda.h>
#include <cuda_fp16.h>
#include <math.h>
#include <cstdint>

#define NN   20000
#define EE   320000
#define ETOT 340000
#define FIN  384
#define F1   1024
#define HH1  4
#define HD   256
#define F2   256
#define PHID 128
#define NSPLIT 10112          // 79 row tiles of 128
#define TLO 79
#define THI 78                // ceil(20000/128)=157 total tiles

// ---------------- scratch (static device globals; no runtime alloc) ----------
__device__ float g_h1[(size_t)NN * F1];
__device__ float g_h2[(size_t)NN * F2];
__device__ float g_y [(size_t)NN * PHID];
__device__ float g_ss1[NN * HH1];
__device__ float g_sd1[NN * HH1];
__device__ float g_ss2[NN];
__device__ float g_sd2[NN];
__device__ int   g_deg[NN];
__device__ int   g_off[NN + 1];
__device__ int   g_cur[NN];
__device__ int   g_csrc[ETOT];
// fp16 operand planes (A row-major [M,K]; B transposed [N,K])
__device__ __align__(128) __half g_xh [(size_t)NN * FIN];
__device__ __align__(128) __half g_w1h[(size_t)F1 * FIN];
__device__ __align__(128) __half g_o1h[(size_t)NN * F1];
__device__ __align__(128) __half g_w2h[(size_t)F2 * F1];
__device__ __align__(128) __half g_hh [(size_t)NN * F2];
__device__ __align__(128) __half g_wph[(size_t)PHID * F2];

// ---------------- helpers ----------------
__device__ __forceinline__ uint32_t smem_u32(const void* p) {
    uint32_t a;
    asm("{ .reg .u64 t; cvta.to.shared.u64 t, %1; cvt.u32.u64 %0, t; }" : "=r"(a) : "l"(p));
    return a;
}
__device__ __forceinline__ void ldm4(uint32_t* r, uint32_t a) {
    asm volatile("ldmatrix.sync.aligned.m8n8.x4.shared.b16 {%0,%1,%2,%3}, [%4];"
                 : "=r"(r[0]), "=r"(r[1]), "=r"(r[2]), "=r"(r[3]) : "r"(a));
}
__device__ __forceinline__ void mma16816(float* c, const uint32_t* a, uint32_t b0, uint32_t b1) {
    asm volatile("mma.sync.aligned.m16n8k16.row.col.f32.f16.f16.f32 "
                 "{%0,%1,%2,%3}, {%4,%5,%6,%7}, {%8,%9}, {%0,%1,%2,%3};"
                 : "+f"(c[0]), "+f"(c[1]), "+f"(c[2]), "+f"(c[3])
                 : "r"(a[0]), "r"(a[1]), "r"(a[2]), "r"(a[3]), "r"(b0), "r"(b1));
}
#define MBARRIER_INIT(mb, c) \
    asm volatile("mbarrier.init.shared.b64 [%0], %1;" :: "r"((uint32_t)(mb)), "r"((uint32_t)(c)) : "memory")
#define MBARRIER_EXPECT_TX(mb, b) \
    asm volatile("mbarrier.arrive.expect_tx.shared.b64 _, [%0], %1;" \
                 :: "r"((uint32_t)(mb)), "r"((uint32_t)(b)) : "memory")
#define MBARRIER_WAIT_PARITY(mb, par) do { \
    uint32_t _m = (uint32_t)(mb), _p = (uint32_t)(par), _d; \
    asm volatile("{\n\t.reg .pred p;\n\t" \
        "mbarrier.try_wait.parity.acquire.cta.shared::cta.b64 p, [%1], %2;\n\t" \
        "selp.b32 %0, 1, 0, p;\n\t}" : "=r"(_d) : "r"(_m), "r"(_p) : "memory"); \
    if (!_d) { \
        asm volatile("{\n\t.reg .pred P1;\n\tWL_%=:\n\t" \
            "mbarrier.try_wait.parity.acquire.cta.shared::cta.b64 P1, [%0], %1, 0x989680;\n\t" \
            "@P1 bra.uni WD_%=;\n\tbra.uni WL_%=;\n\tWD_%=:\n\t}" \
            :: "r"(_m), "r"(_p) : "memory"); \
    } } while (0)
__device__ __forceinline__ void tma2d(uint32_t dst, const void* map, int x, int y, uint32_t mb) {
    asm volatile(
        "cp.async.bulk.tensor.2d.shared::cta.global.tile.mbarrier::complete_tx::bytes "
        "[%0], [%1, {%2, %3}], [%4];"
        :: "r"(dst), "l"(map), "r"(x), "r"(y), "r"(mb) : "memory");
}
#define SW128(o) ((o) ^ (((o) >> 3) & 0x70u))

// ---------------- fp16 cast + zero kernels ----------------
__global__ void k_cast(const float* __restrict__ in, __half* __restrict__ o, int total) {
    int i = blockIdx.x * blockDim.x + threadIdx.x;
    if (i < total) o[i] = __float2half_rn(in[i]);
}
__global__ void k_castT(const float* __restrict__ W, __half* __restrict__ o, int K, int N) {
    int i = blockIdx.x * blockDim.x + threadIdx.x;
    if (i >= K * N) return;
    int k = i / N, n = i % N;
    o[(size_t)n * K + k] = __float2half_rn(W[i]);
}
__global__ void k_zero4(float* a, float* b, float* c, float* d, int n1, int n2) {
    int i = blockIdx.x * blockDim.x + threadIdx.x;
    if (i < n1) { a[i] = 0.f; b[i] = 0.f; }
    if (i < n2) { c[i] = 0.f; d[i] = 0.f; }
}

// ============== TMA HMMA GEMM: C[M,N] = A[M,K] @ B[N,K]^T ====================
// fp16 in, fp32 accum/out. CTA 128x128, BK=64 (SW128), 3-stage TMA pipeline,
// 8 warps (32x64 each), 2 CTAs/SM. ytile0 = row-tile offset for split launches.
// Optional fused attention logits: ss[m,h] += sum_c C[m,c]*av[h*256+c%256]
// (head width 256; CTA column tile lies in one head since bn % 128 == 0).
#define TG_STAGE 32768
#define TG_SMEM (1024 + 3 * TG_STAGE)

__global__ void __launch_bounds__(256, 2)
hgemm_tma(const __grid_constant__ CUtensorMap mA,
          const __grid_constant__ CUtensorMap mB,
          float* __restrict__ C, int M, int N, int K, int ytile0,
          float* __restrict__ ss, float* __restrict__ sd,
          const float* __restrict__ av, const float* __restrict__ bv) {
    extern __shared__ unsigned char smraw[];
    const uint32_t base0 = (smem_u32(smraw) + 1023u) & ~1023u;
    const uint32_t mbb = base0;
    const uint32_t tile0 = base0 + 1024;
    const int tid = threadIdx.x, wid = tid >> 5, lane = tid & 31;
    const int bm = (blockIdx.y + ytile0) * 128, bn = blockIdx.x * 128;
    const int wr = (wid >> 1) * 32, wn = (wid & 1) * 64;
    const int nc = K >> 6;

    if (tid == 0) {
        MBARRIER_INIT(mbb + 0, 1);
        MBARRIER_INIT(mbb + 8, 1);
        MBARRIER_INIT(mbb + 16, 1);
    }
    __syncthreads();

    if (tid == 0) {
#pragma unroll
        for (int s = 0; s < 2; s++) {
            uint32_t mb = mbb + 8u * s;
            uint32_t t = tile0 + (uint32_t)s * TG_STAGE;
            MBARRIER_EXPECT_TX(mb, TG_STAGE);
            tma2d(t,          &mA, s * 64, bm, mb);
            tma2d(t + 16384u, &mB, s * 64, bn, mb);
        }
    }

    float acc[2][8][4];
#pragma unroll
    for (int a = 0; a < 2; a++)
#pragma unroll
        for (int b = 0; b < 8; b++)
#pragma unroll
            for (int c = 0; c < 4; c++) acc[a][b][c] = 0.f;

    for (int i = 0; i < nc; i++) {
        const int b = i % 3;
        MBARRIER_WAIT_PARITY(mbb + 8u * b, (i / 3) & 1);
        __syncthreads();
        if (tid == 0 && i + 2 < nc) {
            const int nb = (i + 2) % 3;
            uint32_t mb = mbb + 8u * nb;
            uint32_t t = tile0 + (uint32_t)nb * TG_STAGE;
            MBARRIER_EXPECT_TX(mb, TG_STAGE);
            tma2d(t,          &mA, (i + 2) * 64, bm, mb);
            tma2d(t + 16384u, &mB, (i + 2) * 64, bn, mb);
        }

        const uint32_t tA = tile0 + (uint32_t)b * TG_STAGE;
        const uint32_t tB = tA + 16384u;
        const int gq = lane >> 3;
#pragma unroll
        for (int ks = 0; ks < 4; ks++) {
            uint32_t ar[2][4], br[4][4];
#pragma unroll
            for (int mt = 0; mt < 2; mt++) {
                uint32_t lin = (uint32_t)(wr + mt * 16 + (lane & 15)) * 128u
                             + (uint32_t)(ks * 32 + (lane >> 4) * 16);
                ldm4(ar[mt], tA + SW128(lin));
            }
#pragma unroll
            for (int bt = 0; bt < 4; bt++) {
                uint32_t lin = (uint32_t)(wn + bt * 16 + ((gq >> 1) << 3) + (lane & 7)) * 128u
                             + (uint32_t)(ks * 32 + (gq & 1) * 16);
                ldm4(br[bt], tB + SW128(lin));
            }
#pragma unroll
            for (int mt = 0; mt < 2; mt++)
#pragma unroll
                for (int j = 0; j < 8; j++) {
                    const int bt = j >> 1, p0 = (j & 1) * 2;
                    mma16816(acc[mt][j], ar[mt], br[bt][p0], br[bt][p0 + 1]);
                }
        }
    }

    // epilogue: fp32 stores
#pragma unroll
    for (int mt = 0; mt < 2; mt++) {
        int m0 = bm + wr + mt * 16 + (lane >> 2);
#pragma unroll
        for (int j = 0; j < 8; j++) {
            int n0 = bn + wn + j * 8 + (lane & 3) * 2;
            if (m0 < M)
                *(float2*)&C[(size_t)m0 * N + n0] = make_float2(acc[mt][j][0], acc[mt][j][1]);
            if (m0 + 8 < M)
                *(float2*)&C[(size_t)(m0 + 8) * N + n0] = make_float2(acc[mt][j][2], acc[mt][j][3]);
        }
    }

    // fused attention-logit partials
    if (ss) {
        const int Hh = N >> 8;            // heads (head width 256)
        const int h = bn >> 8;
        const int cb0 = (bn & 255) + wn + (lane & 3) * 2;   // col within head
#pragma unroll
        for (int mt = 0; mt < 2; mt++) {
            int m0 = bm + wr + mt * 16 + (lane >> 2);
            float ps0 = 0.f, pd0 = 0.f, ps1 = 0.f, pd1 = 0.f;
#pragma unroll
            for (int j = 0; j < 8; j++) {
                int cb = cb0 + j * 8;
                float a0 = av[h * 256 + cb], a1 = av[h * 256 + cb + 1];
                float d0 = bv[h * 256 + cb], d1 = bv[h * 256 + cb + 1];
                ps0 += acc[mt][j][0] * a0 + acc[mt][j][1] * a1;
                pd0 += acc[mt][j][0] * d0 + acc[mt][j][1] * d1;
                ps1 += acc[mt][j][2] * a0 + acc[mt][j][3] * a1;
                pd1 += acc[mt][j][2] * d0 + acc[mt][j][3] * d1;
            }
#pragma unroll
            for (int o = 1; o < 4; o <<= 1) {
                ps0 += __shfl_xor_sync(0xffffffffu, ps0, o);
                pd0 += __shfl_xor_sync(0xffffffffu, pd0, o);
                ps1 += __shfl_xor_sync(0xffffffffu, ps1, o);
                pd1 += __shfl_xor_sync(0xffffffffu, pd1, o);
            }
            if ((lane & 3) == 0) {
                if (m0 < M) {
                    atomicAdd(&ss[m0 * Hh + h], ps0);
                    atomicAdd(&sd[m0 * Hh + h], pd0);
                }
                if (m0 + 8 < M) {
                    atomicAdd(&ss[(m0 + 8) * Hh + h], ps1);
                    atomicAdd(&sd[(m0 + 8) * Hh + h], pd1);
                }
            }
        }
    }
}

// ---------------- CSR build ----------------
__global__ void k_deg_init(int n) {
    int i = blockIdx.x * blockDim.x + threadIdx.x;
    if (i < n) g_deg[i] = 1;
}
__global__ void k_deg_count(const int* __restrict__ dst, int e) {
    int i = blockIdx.x * blockDim.x + threadIdx.x;
    if (i < e) atomicAdd(&g_deg[dst[i]], 1);
}
__global__ void k_scan(int n) {
    __shared__ int sums[1024];
    int tid = threadIdx.x;
    int chunk = (n + 1023) / 1024;
    int lo = tid * chunk, hi = min(lo + chunk, n);
    int s = 0;
    for (int i = lo; i < hi; i++) s += g_deg[i];
    sums[tid] = s;
    __syncthreads();
    for (int d = 1; d < 1024; d <<= 1) {
        int v = (tid >= d) ? sums[tid - d] : 0;
        __syncthreads();
        sums[tid] += v;
        __syncthreads();
    }
    int base = (tid == 0) ? 0 : sums[tid - 1];
    for (int i = lo; i < hi; i++) {
        g_off[i] = base;
        g_cur[i] = base;
        base += g_deg[i];
    }
    if (tid == 1023) g_off[n] = sums[1023];
}
__global__ void k_fill(const int* __restrict__ src, const int* __restrict__ dst, int e, int n) {
    int i = blockIdx.x * blockDim.x + threadIdx.x;
    if (i >= e + n) return;
    int s, d;
    if (i < e) { s = src[i]; d = dst[i]; }
    else       { s = i - e;  d = i - e; }
    int pos = atomicAdd(&g_cur[d], 1);
    g_csrc[pos] = s;
}

// ---------------- per-dst softmax + aggregation + bias + ELU ----------------
__device__ __forceinline__ float lrelu(float x) { return x > 0.f ? x : 0.2f * x; }

template <int H, int C, int PC>   // PC = H*C/256
__global__ void __launch_bounds__(256)
k_agg(const float* __restrict__ feat, const float* __restrict__ ss,
      const float* __restrict__ sd, const float* __restrict__ bias,
      float* __restrict__ out, __half* __restrict__ oh, int d0) {
    constexpr int CAP = 256;
    constexpr int ST  = (H == 4) ? 5 : 1;
    const int d = blockIdx.x + d0;
    const int base = g_off[d], deg = g_off[d + 1] - base;
    const int capped = min(deg, CAP);
    __shared__ float s_m[H], s_inv[H];
    __shared__ float s_e[CAP * ST];
    __shared__ int   s_idx[CAP];
    const int t = threadIdx.x, wid = t >> 5, lane = t & 31;

    // Phase A: cache src indices + raw leaky-relu logits (one gather pass)
    {
        const int jj = (H == 1) ? t : (t >> 2);
        const int h  = (H == 1) ? 0 : (t & 3);
        const float sdv = sd[d * H + h];
        for (int j0 = 0; j0 < capped; j0 += 256 / H) {
            int j = j0 + jj;
            if (j < capped) {
                int s = g_csrc[base + j];
                if (h == 0) s_idx[j] = s;
                s_e[j * ST + h] = lrelu(ss[s * H + h] + sdv);
            }
        }
    }
    __syncthreads();

    // Phase B: per-head max + denominator
    if (wid < H) {
        const int h = wid;
        const float sdv = sd[d * H + h];
        float mx = -1e30f;
        for (int j = lane; j < capped; j += 32) mx = fmaxf(mx, s_e[j * ST + h]);
        for (int j = CAP + lane; j < deg; j += 32) {
            int s = g_csrc[base + j];
            mx = fmaxf(mx, lrelu(ss[s * H + h] + sdv));
        }
#pragma unroll
        for (int o = 16; o; o >>= 1) mx = fmaxf(mx, __shfl_xor_sync(0xffffffffu, mx, o));
        float sm = 0.f;
        for (int j = lane; j < capped; j += 32) sm += expf(s_e[j * ST + h] - mx);
        for (int j = CAP + lane; j < deg; j += 32) {
            int s = g_csrc[base + j];
            sm += expf(lrelu(ss[s * H + h] + sdv) - mx);
        }
#pragma unroll
        for (int o = 16; o; o >>= 1) sm += __shfl_xor_sync(0xffffffffu, sm, o);
        if (lane == 0) { s_m[h] = mx; s_inv[h] = 1.f / (sm + 1e-16f); }
    }
    __syncthreads();

    // Phase C: logits -> normalized weights in place
    {
        const int jj = (H == 1) ? t : (t >> 2);
        const int h  = (H == 1) ? 0 : (t & 3);
        const float mh = s_m[h], iv = s_inv[h];
        for (int j0 = 0; j0 < capped; j0 += 256 / H) {
            int j = j0 + jj;
            if (j < capped) s_e[j * ST + h] = expf(s_e[j * ST + h] - mh) * iv;
        }
    }
    __syncthreads();

    const int hh = (t * PC) / C;
    float acc[PC];
#pragma unroll
    for (int k = 0; k < PC; k++) acc[k] = 0.f;

    // Phase D: accumulate with deep prefetch (4-wide float4 / 8-wide scalar)
    if (PC == 4) {
        const float* fb = feat + t * 4;
        const int RW = H * C;
        float4 b0 = make_float4(0, 0, 0, 0), b1 = b0, b2 = b0, b3 = b0;
        if (capped > 0) b0 = *(const float4*)(fb + (size_t)s_idx[0] * RW);
        if (capped > 1) b1 = *(const float4*)(fb + (size_t)s_idx[1] * RW);
        if (capped > 2) b2 = *(const float4*)(fb + (size_t)s_idx[2] * RW);
        if (capped > 3) b3 = *(const float4*)(fb + (size_t)s_idx[3] * RW);
        int j = 0;
        for (; j + 4 <= capped; j += 4) {
            float w0 = s_e[(j + 0) * ST + hh], w1 = s_e[(j + 1) * ST + hh];
            float w2 = s_e[(j + 2) * ST + hh], w3 = s_e[(j + 3) * ST + hh];
            float4 v0 = b0, v1 = b1, v2 = b2, v3 = b3;
            if (j + 4 < capped) b0 = *(const float4*)(fb + (size_t)s_idx[j + 4] * RW);
            if (j + 5 < capped) b1 = *(const float4*)(fb + (size_t)s_idx[j + 5] * RW);
            if (j + 6 < capped) b2 = *(const float4*)(fb + (size_t)s_idx[j + 6] * RW);
            if (j + 7 < capped) b3 = *(const float4*)(fb + (size_t)s_idx[j + 7] * RW);
            acc[0] += v0.x * w0 + v1.x * w1 + v2.x * w2 + v3.x * w3;
            acc[1] += v0.y * w0 + v1.y * w1 + v2.y * w2 + v3.y * w3;
            acc[2] += v0.z * w0 + v1.z * w1 + v2.z * w2 + v3.z * w3;
            acc[3] += v0.w * w0 + v1.w * w1 + v2.w * w2 + v3.w * w3;
        }
        if (j < capped) {
            float w = s_e[j * ST + hh];
            acc[0] += b0.x * w; acc[1] += b0.y * w; acc[2] += b0.z * w; acc[3] += b0.w * w;
        }
        if (j + 1 < capped) {
            float w = s_e[(j + 1) * ST + hh];
            acc[0] += b1.x * w; acc[1] += b1.y * w; acc[2] += b1.z * w; acc[3] += b1.w * w;
        }
        if (j + 2 < capped) {
            float w = s_e[(j + 2) * ST + hh];
            acc[0] += b2.x * w; acc[1] += b2.y * w; acc[2] += b2.z * w; acc[3] += b2.w * w;
        }
    } else {
        const float* fb = feat + t;
        float c0 = 0, c1 = 0, c2 = 0, c3 = 0, c4 = 0, c5 = 0, c6 = 0, c7 = 0;
        if (capped > 0) c0 = fb[(size_t)s_idx[0] * C];
        if (capped > 1) c1 = fb[(size_t)s_idx[1] * C];
        if (capped > 2) c2 = fb[(size_t)s_idx[2] * C];
        if (capped > 3) c3 = fb[(size_t)s_idx[3] * C];
        if (capped > 4) c4 = fb[(size_t)s_idx[4] * C];
        if (capped > 5) c5 = fb[(size_t)s_idx[5] * C];
        if (capped > 6) c6 = fb[(size_t)s_idx[6] * C];
        if (capped > 7) c7 = fb[(size_t)s_idx[7] * C];
        int j = 0;
        for (; j + 8 <= capped; j += 8) {
            float a0 = c0 * s_e[j + 0] + c1 * s_e[j + 1] + c2 * s_e[j + 2] + c3 * s_e[j + 3];
            float a1 = c4 * s_e[j + 4] + c5 * s_e[j + 5] + c6 * s_e[j + 6] + c7 * s_e[j + 7];
            if (j +  8 < capped) c0 = fb[(size_t)s_idx[j +  8] * C];
            if (j +  9 < capped) c1 = fb[(size_t)s_idx[j +  9] * C];
            if (j + 10 < capped) c2 = fb[(size_t)s_idx[j + 10] * C];
            if (j + 11 < capped) c3 = fb[(size_t)s_idx[j + 11] * C];
            if (j + 12 < capped) c4 = fb[(size_t)s_idx[j + 12] * C];
            if (j + 13 < capped) c5 = fb[(size_t)s_idx[j + 13] * C];
            if (j + 14 < capped) c6 = fb[(size_t)s_idx[j + 14] * C];
            if (j + 15 < capped) c7 = fb[(size_t)s_idx[j + 15] * C];
            acc[0] += a0 + a1;
        }
        if (j     < capped) acc[0] += c0 * s_e[j];
        if (j + 1 < capped) acc[0] += c1 * s_e[j + 1];
        if (j + 2 < capped) acc[0] += c2 * s_e[j + 2];
        if (j + 3 < capped) acc[0] += c3 * s_e[j + 3];
        if (j + 4 < capped) acc[0] += c4 * s_e[j + 4];
        if (j + 5 < capped) acc[0] += c5 * s_e[j + 5];
        if (j + 6 < capped) acc[0] += c6 * s_e[j + 6];
    }

    // Phase E: overflow edges (deg > CAP)
    if (deg > CAP) {
        constexpr int CH = 256 / H;
        for (int j0 = CAP; j0 < deg; j0 += CH) {
            __syncthreads();
            const int cnt = min(CH, deg - j0);
            const int jj = (H == 1) ? t : (t >> 2);
            const int h  = (H == 1) ? 0 : (t & 3);
            if (jj < cnt) {
                int s = g_csrc[base + j0 + jj];
                if (h == 0) s_idx[jj] = s;
                s_e[jj * ST + h] =
                    expf(lrelu(ss[s * H + h] + sd[d * H + h]) - s_m[h]) * s_inv[h];
            }
            __syncthreads();
            for (int j = 0; j < cnt; j++) {
                int s = s_idx[j];
                float w = s_e[j * ST + hh];
                if (PC == 4) {
                    float4 v = *(const float4*)&feat[(size_t)s * H * C + t * 4];
                    acc[0] += v.x * w; acc[1] += v.y * w;
                    acc[2] += v.z * w; acc[3] += v.w * w;
                } else {
                    acc[0] += feat[(size_t)s * C + t] * w;
                }
            }
        }
    }

    const int HC = H * C;
#pragma unroll
    for (int k = 0; k < PC; k++) {
        int c = t * PC + k;
        float v = acc[k] + bias[c];
        v = v > 0.f ? v : expm1f(v);
        if (out) out[(size_t)d * HC + c] = v;
        oh[(size_t)d * HC + c] = __float2half_rn(v);
    }
}

// ---------------- graph mean + influence head ----------------
__global__ void k_zero_gf(float* gf) { gf[threadIdx.x] = 0.f; }
__global__ void k_colsum(const float* __restrict__ h, float* __restrict__ gf) {
    float acc = 0.f;
    int t = threadIdx.x;
    for (int r = blockIdx.x; r < NN; r += gridDim.x) acc += h[(size_t)r * F2 + t];
    atomicAdd(&gf[t], acc);
}
__global__ void k_scale_gf(float* gf) { gf[threadIdx.x] *= (1.0f / (float)NN); }

__global__ void k_infl(const float* __restrict__ y, const float* __restrict__ bp1,
                       const float* __restrict__ wp2, const float* __restrict__ bp2,
                       float* __restrict__ infl, int n) {
    int w = (blockIdx.x * blockDim.x + threadIdx.x) >> 5;
    int lane = threadIdx.x & 31;
    if (w >= n) return;
    float acc = 0.f;
    for (int j = lane; j < PHID; j += 32) {
        float v = y[(size_t)w * PHID + j] + bp1[j];
        v = v > 0.f ? v : 0.f;
        acc += v * wp2[j];
    }
#pragma unroll
    for (int o = 16; o; o >>= 1) acc += __shfl_xor_sync(0xffffffffu, acc, o);
    if (lane == 0) infl[w] = 1.f / (1.f + expf(-(acc + bp2[0])));
}

// ---------------- host: tensor-map builder ----------------
typedef CUresult (*PFN_encodeTiled)(
    CUtensorMap*, CUtensorMapDataType, cuuint32_t, void*,
    const cuuint64_t*, const cuuint64_t*, const cuuint32_t*, const cuuint32_t*,
    CUtensorMapInterleave, CUtensorMapSwizzle, CUtensorMapL2promotion,
    CUtensorMapFloatOOBfill);

static CUtensorMap make_map(PFN_encodeTiled enc, void* base, int K, int rows) {
    CUtensorMap m;
    cuuint64_t dims[2]    = {(cuuint64_t)K, (cuuint64_t)rows};
    cuuint64_t strides[1] = {(cuuint64_t)K * 2};
    cuuint32_t box[2]     = {64, 128};
    cuuint32_t es[2]      = {1, 1};
    enc(&m, CU_TENSOR_MAP_DATA_TYPE_FLOAT16, 2, base, dims, strides, box, es,
        CU_TENSOR_MAP_INTERLEAVE_NONE, CU_TENSOR_MAP_SWIZZLE_128B,
        CU_TENSOR_MAP_L2_PROMOTION_L2_128B, CU_TENSOR_MAP_FLOAT_OOB_FILL_NONE);
    return m;
}

// ---------------- launch ----------------
extern "C" void kernel_launch(void* const* d_in, const int* in_sizes, int n_in,
                              void* d_out, int out_size) {
    const float* x   = (const float*)d_in[0];
    const int*   eidx = (const int*)d_in[1];
    const float* W1  = (const float*)d_in[2];
    const float* as1 = (const float*)d_in[3];
    const float* ad1 = (const float*)d_in[4];
    const float* b1  = (const float*)d_in[5];
    const float* W2  = (const float*)d_in[6];
    const float* as2 = (const float*)d_in[7];
    const float* ad2 = (const float*)d_in[8];
    const float* b2  = (const float*)d_in[9];
    const float* Wp1 = (const float*)d_in[10];
    const float* bp1 = (const float*)d_in[11];
    const float* Wp2 = (const float*)d_in[12];
    const float* bp2 = (const float*)d_in[13];

    const int* src = eidx;
    const int* dst = eidx + EE;

    float* out   = (float*)d_out;
    float* out_h = out;
    float* out_g = out + (size_t)NN * F2;
    float* out_i = out_g + F2;

    float *p_h1, *p_h2, *p_y, *p_ss1, *p_sd1, *p_ss2, *p_sd2;
    __half *p_xh, *p_w1h, *p_o1h, *p_w2h, *p_hh, *p_wph;
    cudaGetSymbolAddress((void**)&p_h1, g_h1);
    cudaGetSymbolAddress((void**)&p_h2, g_h2);
    cudaGetSymbolAddress((void**)&p_y,  g_y);
    cudaGetSymbolAddress((void**)&p_ss1, g_ss1);
    cudaGetSymbolAddress((void**)&p_sd1, g_sd1);
    cudaGetSymbolAddress((void**)&p_ss2, g_ss2);
    cudaGetSymbolAddress((void**)&p_sd2, g_sd2);
    cudaGetSymbolAddress((void**)&p_xh,  g_xh);
    cudaGetSymbolAddress((void**)&p_w1h, g_w1h);
    cudaGetSymbolAddress((void**)&p_o1h, g_o1h);
    cudaGetSymbolAddress((void**)&p_w2h, g_w2h);
    cudaGetSymbolAddress((void**)&p_hh,  g_hh);
    cudaGetSymbolAddress((void**)&p_wph, g_wph);

    PFN_encodeTiled enc = nullptr;
    cudaGetDriverEntryPoint("cuTensorMapEncodeTiled", (void**)&enc, cudaEnableDefault);

    CUtensorMap mA1 = make_map(enc, p_xh,  FIN, NN);
    CUtensorMap mB1 = make_map(enc, p_w1h, FIN, F1);
    CUtensorMap mA2 = make_map(enc, p_o1h, F1,  NN);
    CUtensorMap mB2 = make_map(enc, p_w2h, F1,  F2);
    CUtensorMap mA3 = make_map(enc, p_hh,  F2,  NN);
    CUtensorMap mB3 = make_map(enc, p_wph, F2, PHID);

    cudaFuncSetAttribute(hgemm_tma, cudaFuncAttributeMaxDynamicSharedMemorySize, TG_SMEM);

    static cudaStream_t s1 = nullptr;
    static cudaEvent_t evF1 = nullptr, evJ1 = nullptr, evA1lo = nullptr,
                       evS1a = nullptr, evA2lo = nullptr, evA2hi = nullptr,
                       evJ2 = nullptr;
    if (!s1) {
        cudaStreamCreateWithFlags(&s1, cudaStreamNonBlocking);
        cudaEventCreateWithFlags(&evF1,  cudaEventDisableTiming);
        cudaEventCreateWithFlags(&evJ1,  cudaEventDisableTiming);
        cudaEventCreateWithFlags(&evA1lo, cudaEventDisableTiming);
        cudaEventCreateWithFlags(&evS1a, cudaEventDisableTiming);
        cudaEventCreateWithFlags(&evA2lo, cudaEventDisableTiming);
        cudaEventCreateWithFlags(&evA2hi, cudaEventDisableTiming);
        cudaEventCreateWithFlags(&evJ2,  cudaEventDisableTiming);
    }

    // ---- fork 1: CSR build + later-weight casts beside GEMM1 path ----
    cudaEventRecord(evF1, 0);
    cudaStreamWaitEvent(s1, evF1, 0);
    k_castT<<<(F1 * F2 + 255) / 256, 256, 0, s1>>>(W2, p_w2h, F1, F2);
    k_castT<<<(F2 * PHID + 255) / 256, 256, 0, s1>>>(Wp1, p_wph, F2, PHID);
    k_deg_init <<<(NN + 255) / 256, 256, 0, s1>>>(NN);
    k_deg_count<<<(EE + 255) / 256, 256, 0, s1>>>(dst, EE);
    k_scan<<<1, 1024, 0, s1>>>(NN);
    k_fill<<<(ETOT + 255) / 256, 256, 0, s1>>>(src, dst, EE, NN);
    cudaEventRecord(evJ1, s1);

    // ---- main: zero logits, casts -> GEMM1 (fused ss1/sd1) ----
    k_zero4<<<(NN * HH1 + 255) / 256, 256>>>(p_ss1, p_sd1, p_ss2, p_sd2, NN * HH1, NN);
    k_cast <<<(NN * FIN + 255) / 256, 256>>>(x, p_xh, NN * FIN);
    k_castT<<<(FIN * F1 + 255) / 256, 256>>>(W1, p_w1h, FIN, F1);
    hgemm_tma<<<dim3(F1 / 128, TLO + THI), 256, TG_SMEM>>>(mA1, mB1, p_h1, NN, F1, FIN, 0,
                                                           p_ss1, p_sd1, as1, ad1);
    cudaStreamWaitEvent(0, evJ1, 0);

    // ---- agg1 split-pipeline with GEMM2 (fused ss2/sd2) ----
    k_agg<HH1, HD, 4><<<NSPLIT, 256>>>(p_h1, p_ss1, p_sd1, b1, nullptr, p_o1h, 0);
    cudaEventRecord(evA1lo, 0);
    cudaStreamWaitEvent(s1, evA1lo, 0);
    hgemm_tma<<<dim3(F2 / 128, TLO), 256, TG_SMEM, s1>>>(mA2, mB2, p_h2, NN, F2, F1, 0,
                                                         p_ss2, p_sd2, as2, ad2);
    cudaEventRecord(evS1a, s1);

    k_agg<HH1, HD, 4><<<NN - NSPLIT, 256>>>(p_h1, p_ss1, p_sd1, b1, nullptr, p_o1h, NSPLIT);
    hgemm_tma<<<dim3(F2 / 128, THI), 256, TG_SMEM>>>(mA2, mB2, p_h2, NN, F2, F1, TLO,
                                                     p_ss2, p_sd2, as2, ad2);
    cudaStreamWaitEvent(0, evS1a, 0);

    // ---- agg2 split-pipeline with GEMM3 + infl ----
    k_agg<1, F2, 1><<<NSPLIT, 256>>>(p_h2, p_ss2, p_sd2, b2, out_h, p_hh, 0);
    cudaEventRecord(evA2lo, 0);
    cudaStreamWaitEvent(s1, evA2lo, 0);
    hgemm_tma<<<dim3(PHID / 128, TLO), 256, TG_SMEM, s1>>>(mA3, mB3, p_y, NN, PHID, F2, 0,
                                                           nullptr, nullptr, nullptr, nullptr);
    k_infl<<<(NSPLIT * 32 + 255) / 256, 256, 0, s1>>>(p_y, bp1, Wp2, bp2, out_i, NSPLIT);

    k_agg<1, F2, 1><<<NN - NSPLIT, 256>>>(p_h2, p_ss2, p_sd2, b2, out_h, p_hh, NSPLIT);
    cudaEventRecord(evA2hi, 0);

    // side: graph mean (needs full out_h)
    cudaStreamWaitEvent(s1, evA2hi, 0);
    k_zero_gf<<<1, F2, 0, s1>>>(out_g);
    k_colsum<<<160, F2, 0, s1>>>(out_h, out_g);
    k_scale_gf<<<1, F2, 0, s1>>>(out_g);
    cudaEventRecord(evJ2, s1);

    // main: GEMM3_hi + infl_hi
    hgemm_tma<<<dim3(PHID / 128, THI), 256, TG_SMEM>>>(mA3, mB3, p_y, NN, PHID, F2, TLO,
                                                       nullptr, nullptr, nullptr, nullptr);
    k_infl<<<((NN - NSPLIT) * 32 + 255) / 256, 256>>>(p_y + (size_t)NSPLIT * PHID, bp1, Wp2, bp2,
                                                      out_i + NSPLIT, NN - NSPLIT);
    cudaStreamWaitEvent(0, evJ2, 0);
}

// round 11
// speedup vs baseline: 1.2332x; 1.0228x over previous
#include <cuda_runtime.h>
#include <cuda.h>
#include <cuda_fp16.h>
#include <math.h>
#include <cstdint>

#define NN   20000
#define EE   320000
#define ETOT 340000
#define FIN  384
#define F1   1024
#define HH1  4
#define HD   256
#define F2   256
#define PHID 128
#define NSPLIT 10112          // 79 row tiles of 128
#define TLO 79
#define THI 78                // ceil(20000/128)=157 total tiles

// ---------------- scratch (static device globals; no runtime alloc) ----------
__device__ float g_y [(size_t)NN * PHID];
__device__ float g_ss1[NN * HH1];
__device__ float g_sd1[NN * HH1];
__device__ float g_ss2[NN];
__device__ float g_sd2[NN];
__device__ int   g_deg[NN];
__device__ int   g_off[NN + 1];
__device__ int   g_cur[NN];
__device__ int   g_csrc[ETOT];
// fp16 planes (A row-major [M,K]; B transposed [N,K])
__device__ __align__(128) __half g_xh [(size_t)NN * FIN];
__device__ __align__(128) __half g_w1h[(size_t)F1 * FIN];
__device__ __align__(128) __half g_h1h[(size_t)NN * F1];   // GEMM1 out (fp16 only)
__device__ __align__(128) __half g_o1h[(size_t)NN * F1];   // agg1 out (GEMM2 A)
__device__ __align__(128) __half g_w2h[(size_t)F2 * F1];
__device__ __align__(128) __half g_h2h[(size_t)NN * F2];   // GEMM2 out (fp16 only)
__device__ __align__(128) __half g_hh [(size_t)NN * F2];   // final h fp16 (GEMM3 A)
__device__ __align__(128) __half g_wph[(size_t)PHID * F2];

// ---------------- helpers ----------------
__device__ __forceinline__ uint32_t smem_u32(const void* p) {
    uint32_t a;
    asm("{ .reg .u64 t; cvta.to.shared.u64 t, %1; cvt.u32.u64 %0, t; }" : "=r"(a) : "l"(p));
    return a;
}
__device__ __forceinline__ void ldm4(uint32_t* r, uint32_t a) {
    asm volatile("ldmatrix.sync.aligned.m8n8.x4.shared.b16 {%0,%1,%2,%3}, [%4];"
                 : "=r"(r[0]), "=r"(r[1]), "=r"(r[2]), "=r"(r[3]) : "r"(a));
}
__device__ __forceinline__ void mma16816(float* c, const uint32_t* a, uint32_t b0, uint32_t b1) {
    asm volatile("mma.sync.aligned.m16n8k16.row.col.f32.f16.f16.f32 "
                 "{%0,%1,%2,%3}, {%4,%5,%6,%7}, {%8,%9}, {%0,%1,%2,%3};"
                 : "+f"(c[0]), "+f"(c[1]), "+f"(c[2]), "+f"(c[3])
                 : "r"(a[0]), "r"(a[1]), "r"(a[2]), "r"(a[3]), "r"(b0), "r"(b1));
}
#define MBARRIER_INIT(mb, c) \
    asm volatile("mbarrier.init.shared.b64 [%0], %1;" :: "r"((uint32_t)(mb)), "r"((uint32_t)(c)) : "memory")
#define MBARRIER_EXPECT_TX(mb, b) \
    asm volatile("mbarrier.arrive.expect_tx.shared.b64 _, [%0], %1;" \
                 :: "r"((uint32_t)(mb)), "r"((uint32_t)(b)) : "memory")
#define MBARRIER_WAIT_PARITY(mb, par) do { \
    uint32_t _m = (uint32_t)(mb), _p = (uint32_t)(par), _d; \
    asm volatile("{\n\t.reg .pred p;\n\t" \
        "mbarrier.try_wait.parity.acquire.cta.shared::cta.b64 p, [%1], %2;\n\t" \
        "selp.b32 %0, 1, 0, p;\n\t}" : "=r"(_d) : "r"(_m), "r"(_p) : "memory"); \
    if (!_d) { \
        asm volatile("{\n\t.reg .pred P1;\n\tWL_%=:\n\t" \
            "mbarrier.try_wait.parity.acquire.cta.shared::cta.b64 P1, [%0], %1, 0x989680;\n\t" \
            "@P1 bra.uni WD_%=;\n\tbra.uni WL_%=;\n\tWD_%=:\n\t}" \
            :: "r"(_m), "r"(_p) : "memory"); \
    } } while (0)
__device__ __forceinline__ void tma2d(uint32_t dst, const void* map, int x, int y, uint32_t mb) {
    asm volatile(
        "cp.async.bulk.tensor.2d.shared::cta.global.tile.mbarrier::complete_tx::bytes "
        "[%0], [%1, {%2, %3}], [%4];"
        :: "r"(dst), "l"(map), "r"(x), "r"(y), "r"(mb) : "memory");
}
#define SW128(o) ((o) ^ (((o) >> 3) & 0x70u))

// ---------------- fp16 cast + zero kernels ----------------
__global__ void k_cast(const float* __restrict__ in, __half* __restrict__ o, int total) {
    int i = blockIdx.x * blockDim.x + threadIdx.x;
    if (i < total) o[i] = __float2half_rn(in[i]);
}
__global__ void k_castT(const float* __restrict__ W, __half* __restrict__ o, int K, int N) {
    int i = blockIdx.x * blockDim.x + threadIdx.x;
    if (i >= K * N) return;
    int k = i / N, n = i % N;
    o[(size_t)n * K + k] = __float2half_rn(W[i]);
}
__global__ void k_zero4(float* a, float* b, float* c, float* d, int n1, int n2) {
    int i = blockIdx.x * blockDim.x + threadIdx.x;
    if (i < n1) { a[i] = 0.f; b[i] = 0.f; }
    if (i < n2) { c[i] = 0.f; d[i] = 0.f; }
}

// ============== TMA HMMA GEMM: C[M,N] = A[M,K] @ B[N,K]^T ====================
// fp16 in, fp32 accum. Output: fp32 C and/or fp16 Ch (whichever non-null).
// CTA 128x128, BK=64 (SW128), 3-stage TMA pipeline, 8 warps, 2 CTAs/SM.
// Optional fused attention logits: ss[m,h] += sum_c out[m,c]*av[h*256+c%256].
#define TG_STAGE 32768
#define TG_SMEM (1024 + 3 * TG_STAGE)

__global__ void __launch_bounds__(256, 2)
hgemm_tma(const __grid_constant__ CUtensorMap mA,
          const __grid_constant__ CUtensorMap mB,
          float* __restrict__ C, __half* __restrict__ Ch, int M, int N, int K, int ytile0,
          float* __restrict__ ss, float* __restrict__ sd,
          const float* __restrict__ av, const float* __restrict__ bv) {
    extern __shared__ unsigned char smraw[];
    const uint32_t base0 = (smem_u32(smraw) + 1023u) & ~1023u;
    const uint32_t mbb = base0;
    const uint32_t tile0 = base0 + 1024;
    const int tid = threadIdx.x, wid = tid >> 5, lane = tid & 31;
    const int bm = (blockIdx.y + ytile0) * 128, bn = blockIdx.x * 128;
    const int wr = (wid >> 1) * 32, wn = (wid & 1) * 64;
    const int nc = K >> 6;

    if (tid == 0) {
        MBARRIER_INIT(mbb + 0, 1);
        MBARRIER_INIT(mbb + 8, 1);
        MBARRIER_INIT(mbb + 16, 1);
    }
    __syncthreads();

    if (tid == 0) {
#pragma unroll
        for (int s = 0; s < 2; s++) {
            uint32_t mb = mbb + 8u * s;
            uint32_t t = tile0 + (uint32_t)s * TG_STAGE;
            MBARRIER_EXPECT_TX(mb, TG_STAGE);
            tma2d(t,          &mA, s * 64, bm, mb);
            tma2d(t + 16384u, &mB, s * 64, bn, mb);
        }
    }

    float acc[2][8][4];
#pragma unroll
    for (int a = 0; a < 2; a++)
#pragma unroll
        for (int b = 0; b < 8; b++)
#pragma unroll
            for (int c = 0; c < 4; c++) acc[a][b][c] = 0.f;

    for (int i = 0; i < nc; i++) {
        const int b = i % 3;
        MBARRIER_WAIT_PARITY(mbb + 8u * b, (i / 3) & 1);
        __syncthreads();
        if (tid == 0 && i + 2 < nc) {
            const int nb = (i + 2) % 3;
            uint32_t mb = mbb + 8u * nb;
            uint32_t t = tile0 + (uint32_t)nb * TG_STAGE;
            MBARRIER_EXPECT_TX(mb, TG_STAGE);
            tma2d(t,          &mA, (i + 2) * 64, bm, mb);
            tma2d(t + 16384u, &mB, (i + 2) * 64, bn, mb);
        }

        const uint32_t tA = tile0 + (uint32_t)b * TG_STAGE;
        const uint32_t tB = tA + 16384u;
        const int gq = lane >> 3;
#pragma unroll
        for (int ks = 0; ks < 4; ks++) {
            uint32_t ar[2][4], br[4][4];
#pragma unroll
            for (int mt = 0; mt < 2; mt++) {
                uint32_t lin = (uint32_t)(wr + mt * 16 + (lane & 15)) * 128u
                             + (uint32_t)(ks * 32 + (lane >> 4) * 16);
                ldm4(ar[mt], tA + SW128(lin));
            }
#pragma unroll
            for (int bt = 0; bt < 4; bt++) {
                uint32_t lin = (uint32_t)(wn + bt * 16 + ((gq >> 1) << 3) + (lane & 7)) * 128u
                             + (uint32_t)(ks * 32 + (gq & 1) * 16);
                ldm4(br[bt], tB + SW128(lin));
            }
#pragma unroll
            for (int mt = 0; mt < 2; mt++)
#pragma unroll
                for (int j = 0; j < 8; j++) {
                    const int bt = j >> 1, p0 = (j & 1) * 2;
                    mma16816(acc[mt][j], ar[mt], br[bt][p0], br[bt][p0 + 1]);
                }
        }
    }

    // epilogue: fp32 and/or fp16 stores
#pragma unroll
    for (int mt = 0; mt < 2; mt++) {
        int m0 = bm + wr + mt * 16 + (lane >> 2);
#pragma unroll
        for (int j = 0; j < 8; j++) {
            int n0 = bn + wn + j * 8 + (lane & 3) * 2;
            if (C) {
                if (m0 < M)
                    *(float2*)&C[(size_t)m0 * N + n0] = make_float2(acc[mt][j][0], acc[mt][j][1]);
                if (m0 + 8 < M)
                    *(float2*)&C[(size_t)(m0 + 8) * N + n0] = make_float2(acc[mt][j][2], acc[mt][j][3]);
            }
            if (Ch) {
                if (m0 < M)
                    *(__half2*)&Ch[(size_t)m0 * N + n0] =
                        __floats2half2_rn(acc[mt][j][0], acc[mt][j][1]);
                if (m0 + 8 < M)
                    *(__half2*)&Ch[(size_t)(m0 + 8) * N + n0] =
                        __floats2half2_rn(acc[mt][j][2], acc[mt][j][3]);
            }
        }
    }

    // fused attention-logit partials
    if (ss) {
        const int Hh = N >> 8;            // heads (head width 256)
        const int h = bn >> 8;
        const int cb0 = (bn & 255) + wn + (lane & 3) * 2;   // col within head
#pragma unroll
        for (int mt = 0; mt < 2; mt++) {
            int m0 = bm + wr + mt * 16 + (lane >> 2);
            float ps0 = 0.f, pd0 = 0.f, ps1 = 0.f, pd1 = 0.f;
#pragma unroll
            for (int j = 0; j < 8; j++) {
                int cb = cb0 + j * 8;
                float a0 = av[h * 256 + cb], a1 = av[h * 256 + cb + 1];
                float d0 = bv[h * 256 + cb], d1 = bv[h * 256 + cb + 1];
                ps0 += acc[mt][j][0] * a0 + acc[mt][j][1] * a1;
                pd0 += acc[mt][j][0] * d0 + acc[mt][j][1] * d1;
                ps1 += acc[mt][j][2] * a0 + acc[mt][j][3] * a1;
                pd1 += acc[mt][j][2] * d0 + acc[mt][j][3] * d1;
            }
#pragma unroll
            for (int o = 1; o < 4; o <<= 1) {
                ps0 += __shfl_xor_sync(0xffffffffu, ps0, o);
                pd0 += __shfl_xor_sync(0xffffffffu, pd0, o);
                ps1 += __shfl_xor_sync(0xffffffffu, ps1, o);
                pd1 += __shfl_xor_sync(0xffffffffu, pd1, o);
            }
            if ((lane & 3) == 0) {
                if (m0 < M) {
                    atomicAdd(&ss[m0 * Hh + h], ps0);
                    atomicAdd(&sd[m0 * Hh + h], pd0);
                }
                if (m0 + 8 < M) {
                    atomicAdd(&ss[(m0 + 8) * Hh + h], ps1);
                    atomicAdd(&sd[(m0 + 8) * Hh + h], pd1);
                }
            }
        }
    }
}

// ---------------- CSR build ----------------
__global__ void k_deg_init(int n) {
    int i = blockIdx.x * blockDim.x + threadIdx.x;
    if (i < n) g_deg[i] = 1;
}
__global__ void k_deg_count(const int* __restrict__ dst, int e) {
    int i = blockIdx.x * blockDim.x + threadIdx.x;
    if (i < e) atomicAdd(&g_deg[dst[i]], 1);
}
__global__ void k_scan(int n) {
    __shared__ int sums[1024];
    int tid = threadIdx.x;
    int chunk = (n + 1023) / 1024;
    int lo = tid * chunk, hi = min(lo + chunk, n);
    int s = 0;
    for (int i = lo; i < hi; i++) s += g_deg[i];
    sums[tid] = s;
    __syncthreads();
    for (int d = 1; d < 1024; d <<= 1) {
        int v = (tid >= d) ? sums[tid - d] : 0;
        __syncthreads();
        sums[tid] += v;
        __syncthreads();
    }
    int base = (tid == 0) ? 0 : sums[tid - 1];
    for (int i = lo; i < hi; i++) {
        g_off[i] = base;
        g_cur[i] = base;
        base += g_deg[i];
    }
    if (tid == 1023) g_off[n] = sums[1023];
}
__global__ void k_fill(const int* __restrict__ src, const int* __restrict__ dst, int e, int n) {
    int i = blockIdx.x * blockDim.x + threadIdx.x;
    if (i >= e + n) return;
    int s, d;
    if (i < e) { s = src[i]; d = dst[i]; }
    else       { s = i - e;  d = i - e; }
    int pos = atomicAdd(&g_cur[d], 1);
    g_csrc[pos] = s;
}

// ---------------- per-dst softmax + aggregation + bias + ELU ----------------
// fp16 feature gather; fp32 logits/weights; deep prefetch accumulate.
__device__ __forceinline__ float lrelu(float x) { return x > 0.f ? x : 0.2f * x; }

template <int H, int C, int PC>   // PC = H*C/256
__global__ void __launch_bounds__(256)
k_agg(const __half* __restrict__ feat, const float* __restrict__ ss,
      const float* __restrict__ sd, const float* __restrict__ bias,
      float* __restrict__ out, __half* __restrict__ oh, int d0) {
    constexpr int CAP = 256;
    constexpr int ST  = (H == 4) ? 5 : 1;
    const int d = blockIdx.x + d0;
    const int base = g_off[d], deg = g_off[d + 1] - base;
    const int capped = min(deg, CAP);
    __shared__ float s_m[H], s_inv[H];
    __shared__ float s_e[CAP * ST];
    __shared__ int   s_idx[CAP];
    const int t = threadIdx.x, wid = t >> 5, lane = t & 31;

    // Phase A: cache src indices + raw leaky-relu logits (one gather pass)
    {
        const int jj = (H == 1) ? t : (t >> 2);
        const int h  = (H == 1) ? 0 : (t & 3);
        const float sdv = sd[d * H + h];
        for (int j0 = 0; j0 < capped; j0 += 256 / H) {
            int j = j0 + jj;
            if (j < capped) {
                int s = g_csrc[base + j];
                if (h == 0) s_idx[j] = s;
                s_e[j * ST + h] = lrelu(ss[s * H + h] + sdv);
            }
        }
    }
    __syncthreads();

    // Phase B: per-head max + denominator
    if (wid < H) {
        const int h = wid;
        const float sdv = sd[d * H + h];
        float mx = -1e30f;
        for (int j = lane; j < capped; j += 32) mx = fmaxf(mx, s_e[j * ST + h]);
        for (int j = CAP + lane; j < deg; j += 32) {
            int s = g_csrc[base + j];
            mx = fmaxf(mx, lrelu(ss[s * H + h] + sdv));
        }
#pragma unroll
        for (int o = 16; o; o >>= 1) mx = fmaxf(mx, __shfl_xor_sync(0xffffffffu, mx, o));
        float sm = 0.f;
        for (int j = lane; j < capped; j += 32) sm += expf(s_e[j * ST + h] - mx);
        for (int j = CAP + lane; j < deg; j += 32) {
            int s = g_csrc[base + j];
            sm += expf(lrelu(ss[s * H + h] + sdv) - mx);
        }
#pragma unroll
        for (int o = 16; o; o >>= 1) sm += __shfl_xor_sync(0xffffffffu, sm, o);
        if (lane == 0) { s_m[h] = mx; s_inv[h] = 1.f / (sm + 1e-16f); }
    }
    __syncthreads();

    // Phase C: logits -> normalized weights in place
    {
        const int jj = (H == 1) ? t : (t >> 2);
        const int h  = (H == 1) ? 0 : (t & 3);
        const float mh = s_m[h], iv = s_inv[h];
        for (int j0 = 0; j0 < capped; j0 += 256 / H) {
            int j = j0 + jj;
            if (j < capped) s_e[j * ST + h] = expf(s_e[j * ST + h] - mh) * iv;
        }
    }
    __syncthreads();

    const int hh = (t * PC) / C;
    float acc[PC];
#pragma unroll
    for (int k = 0; k < PC; k++) acc[k] = 0.f;

    // Phase D: fp16 gather accumulate with deep prefetch
    if (PC == 4) {
        const __half* fb = feat + t * 4;
        const int RW = H * C;
        uint2 b0 = make_uint2(0, 0), b1 = b0, b2 = b0, b3 = b0;
        if (capped > 0) b0 = *(const uint2*)(fb + (size_t)s_idx[0] * RW);
        if (capped > 1) b1 = *(const uint2*)(fb + (size_t)s_idx[1] * RW);
        if (capped > 2) b2 = *(const uint2*)(fb + (size_t)s_idx[2] * RW);
        if (capped > 3) b3 = *(const uint2*)(fb + (size_t)s_idx[3] * RW);
        int j = 0;
        for (; j + 4 <= capped; j += 4) {
            float w0 = s_e[(j + 0) * ST + hh], w1 = s_e[(j + 1) * ST + hh];
            float w2 = s_e[(j + 2) * ST + hh], w3 = s_e[(j + 3) * ST + hh];
            float2 v0a = __half22float2(*(const __half2*)&b0.x);
            float2 v0b = __half22float2(*(const __half2*)&b0.y);
            float2 v1a = __half22float2(*(const __half2*)&b1.x);
            float2 v1b = __half22float2(*(const __half2*)&b1.y);
            float2 v2a = __half22float2(*(const __half2*)&b2.x);
            float2 v2b = __half22float2(*(const __half2*)&b2.y);
            float2 v3a = __half22float2(*(const __half2*)&b3.x);
            float2 v3b = __half22float2(*(const __half2*)&b3.y);
            if (j + 4 < capped) b0 = *(const uint2*)(fb + (size_t)s_idx[j + 4] * RW);
            if (j + 5 < capped) b1 = *(const uint2*)(fb + (size_t)s_idx[j + 5] * RW);
            if (j + 6 < capped) b2 = *(const uint2*)(fb + (size_t)s_idx[j + 6] * RW);
            if (j + 7 < capped) b3 = *(const uint2*)(fb + (size_t)s_idx[j + 7] * RW);
            acc[0] += v0a.x * w0 + v1a.x * w1 + v2a.x * w2 + v3a.x * w3;
            acc[1] += v0a.y * w0 + v1a.y * w1 + v2a.y * w2 + v3a.y * w3;
            acc[2] += v0b.x * w0 + v1b.x * w1 + v2b.x * w2 + v3b.x * w3;
            acc[3] += v0b.y * w0 + v1b.y * w1 + v2b.y * w2 + v3b.y * w3;
        }
        for (int r = 0; r < 3 && j + r < capped; r++) {
            uint2 bb = (r == 0) ? b0 : (r == 1) ? b1 : b2;
            float w = s_e[(j + r) * ST + hh];
            float2 fa = __half22float2(*(const __half2*)&bb.x);
            float2 fbv = __half22float2(*(const __half2*)&bb.y);
            acc[0] += fa.x * w; acc[1] += fa.y * w;
            acc[2] += fbv.x * w; acc[3] += fbv.y * w;
        }
    } else {
        const __half* fb = feat + t;
        float c0 = 0, c1 = 0, c2 = 0, c3 = 0, c4 = 0, c5 = 0, c6 = 0, c7 = 0;
        if (capped > 0) c0 = __half2float(fb[(size_t)s_idx[0] * C]);
        if (capped > 1) c1 = __half2float(fb[(size_t)s_idx[1] * C]);
        if (capped > 2) c2 = __half2float(fb[(size_t)s_idx[2] * C]);
        if (capped > 3) c3 = __half2float(fb[(size_t)s_idx[3] * C]);
        if (capped > 4) c4 = __half2float(fb[(size_t)s_idx[4] * C]);
        if (capped > 5) c5 = __half2float(fb[(size_t)s_idx[5] * C]);
        if (capped > 6) c6 = __half2float(fb[(size_t)s_idx[6] * C]);
        if (capped > 7) c7 = __half2float(fb[(size_t)s_idx[7] * C]);
        int j = 0;
        for (; j + 8 <= capped; j += 8) {
            float a0 = c0 * s_e[j + 0] + c1 * s_e[j + 1] + c2 * s_e[j + 2] + c3 * s_e[j + 3];
            float a1 = c4 * s_e[j + 4] + c5 * s_e[j + 5] + c6 * s_e[j + 6] + c7 * s_e[j + 7];
            if (j +  8 < capped) c0 = __half2float(fb[(size_t)s_idx[j +  8] * C]);
            if (j +  9 < capped) c1 = __half2float(fb[(size_t)s_idx[j +  9] * C]);
            if (j + 10 < capped) c2 = __half2float(fb[(size_t)s_idx[j + 10] * C]);
            if (j + 11 < capped) c3 = __half2float(fb[(size_t)s_idx[j + 11] * C]);
            if (j + 12 < capped) c4 = __half2float(fb[(size_t)s_idx[j + 12] * C]);
            if (j + 13 < capped) c5 = __half2float(fb[(size_t)s_idx[j + 13] * C]);
            if (j + 14 < capped) c6 = __half2float(fb[(size_t)s_idx[j + 14] * C]);
            if (j + 15 < capped) c7 = __half2float(fb[(size_t)s_idx[j + 15] * C]);
            acc[0] += a0 + a1;
        }
        if (j     < capped) acc[0] += c0 * s_e[j];
        if (j + 1 < capped) acc[0] += c1 * s_e[j + 1];
        if (j + 2 < capped) acc[0] += c2 * s_e[j + 2];
        if (j + 3 < capped) acc[0] += c3 * s_e[j + 3];
        if (j + 4 < capped) acc[0] += c4 * s_e[j + 4];
        if (j + 5 < capped) acc[0] += c5 * s_e[j + 5];
        if (j + 6 < capped) acc[0] += c6 * s_e[j + 6];
    }

    // Phase E: overflow edges (deg > CAP)
    if (deg > CAP) {
        constexpr int CH = 256 / H;
        for (int j0 = CAP; j0 < deg; j0 += CH) {
            __syncthreads();
            const int cnt = min(CH, deg - j0);
            const int jj = (H == 1) ? t : (t >> 2);
            const int h  = (H == 1) ? 0 : (t & 3);
            if (jj < cnt) {
                int s = g_csrc[base + j0 + jj];
                if (h == 0) s_idx[jj] = s;
                s_e[jj * ST + h] =
                    expf(lrelu(ss[s * H + h] + sd[d * H + h]) - s_m[h]) * s_inv[h];
            }
            __syncthreads();
            for (int j = 0; j < cnt; j++) {
                int s = s_idx[j];
                float w = s_e[j * ST + hh];
                if (PC == 4) {
                    uint2 v = *(const uint2*)&feat[(size_t)s * H * C + t * 4];
                    float2 f0 = __half22float2(*(const __half2*)&v.x);
                    float2 f1 = __half22float2(*(const __half2*)&v.y);
                    acc[0] += f0.x * w; acc[1] += f0.y * w;
                    acc[2] += f1.x * w; acc[3] += f1.y * w;
                } else {
                    acc[0] += __half2float(feat[(size_t)s * C + t]) * w;
                }
            }
        }
    }

    const int HC = H * C;
#pragma unroll
    for (int k = 0; k < PC; k++) {
        int c = t * PC + k;
        float v = acc[k] + bias[c];
        v = v > 0.f ? v : expm1f(v);
        if (out) out[(size_t)d * HC + c] = v;
        oh[(size_t)d * HC + c] = __float2half_rn(v);
    }
}

// ---------------- graph mean + influence head ----------------
__global__ void k_zero_gf(float* gf) { gf[threadIdx.x] = 0.f; }
__global__ void k_colsum(const float* __restrict__ h, float* __restrict__ gf) {
    float acc = 0.f;
    int t = threadIdx.x;
    for (int r = blockIdx.x; r < NN; r += gridDim.x) acc += h[(size_t)r * F2 + t];
    atomicAdd(&gf[t], acc);
}
__global__ void k_scale_gf(float* gf) { gf[threadIdx.x] *= (1.0f / (float)NN); }

__global__ void k_infl(const float* __restrict__ y, const float* __restrict__ bp1,
                       const float* __restrict__ wp2, const float* __restrict__ bp2,
                       float* __restrict__ infl, int n) {
    int w = (blockIdx.x * blockDim.x + threadIdx.x) >> 5;
    int lane = threadIdx.x & 31;
    if (w >= n) return;
    float acc = 0.f;
    for (int j = lane; j < PHID; j += 32) {
        float v = y[(size_t)w * PHID + j] + bp1[j];
        v = v > 0.f ? v : 0.f;
        acc += v * wp2[j];
    }
#pragma unroll
    for (int o = 16; o; o >>= 1) acc += __shfl_xor_sync(0xffffffffu, acc, o);
    if (lane == 0) infl[w] = 1.f / (1.f + expf(-(acc + bp2[0])));
}

// ---------------- host: tensor-map builder ----------------
typedef CUresult (*PFN_encodeTiled)(
    CUtensorMap*, CUtensorMapDataType, cuuint32_t, void*,
    const cuuint64_t*, const cuuint64_t*, const cuuint32_t*, const cuuint32_t*,
    CUtensorMapInterleave, CUtensorMapSwizzle, CUtensorMapL2promotion,
    CUtensorMapFloatOOBfill);

static CUtensorMap make_map(PFN_encodeTiled enc, void* base, int K, int rows) {
    CUtensorMap m;
    cuuint64_t dims[2]    = {(cuuint64_t)K, (cuuint64_t)rows};
    cuuint64_t strides[1] = {(cuuint64_t)K * 2};
    cuuint32_t box[2]     = {64, 128};
    cuuint32_t es[2]      = {1, 1};
    enc(&m, CU_TENSOR_MAP_DATA_TYPE_FLOAT16, 2, base, dims, strides, box, es,
        CU_TENSOR_MAP_INTERLEAVE_NONE, CU_TENSOR_MAP_SWIZZLE_128B,
        CU_TENSOR_MAP_L2_PROMOTION_L2_128B, CU_TENSOR_MAP_FLOAT_OOB_FILL_NONE);
    return m;
}

// ---------------- launch ----------------
extern "C" void kernel_launch(void* const* d_in, const int* in_sizes, int n_in,
                              void* d_out, int out_size) {
    const float* x   = (const float*)d_in[0];
    const int*   eidx = (const int*)d_in[1];
    const float* W1  = (const float*)d_in[2];
    const float* as1 = (const float*)d_in[3];
    const float* ad1 = (const float*)d_in[4];
    const float* b1  = (const float*)d_in[5];
    const float* W2  = (const float*)d_in[6];
    const float* as2 = (const float*)d_in[7];
    const float* ad2 = (const float*)d_in[8];
    const float* b2  = (const float*)d_in[9];
    const float* Wp1 = (const float*)d_in[10];
    const float* bp1 = (const float*)d_in[11];
    const float* Wp2 = (const float*)d_in[12];
    const float* bp2 = (const float*)d_in[13];

    const int* src = eidx;
    const int* dst = eidx + EE;

    float* out   = (float*)d_out;
    float* out_h = out;
    float* out_g = out + (size_t)NN * F2;
    float* out_i = out_g + F2;

    float *p_y, *p_ss1, *p_sd1, *p_ss2, *p_sd2;
    __half *p_xh, *p_w1h, *p_h1h, *p_o1h, *p_w2h, *p_h2h, *p_hh, *p_wph;
    cudaGetSymbolAddress((void**)&p_y,  g_y);
    cudaGetSymbolAddress((void**)&p_ss1, g_ss1);
    cudaGetSymbolAddress((void**)&p_sd1, g_sd1);
    cudaGetSymbolAddress((void**)&p_ss2, g_ss2);
    cudaGetSymbolAddress((void**)&p_sd2, g_sd2);
    cudaGetSymbolAddress((void**)&p_xh,  g_xh);
    cudaGetSymbolAddress((void**)&p_w1h, g_w1h);
    cudaGetSymbolAddress((void**)&p_h1h, g_h1h);
    cudaGetSymbolAddress((void**)&p_o1h, g_o1h);
    cudaGetSymbolAddress((void**)&p_w2h, g_w2h);
    cudaGetSymbolAddress((void**)&p_h2h, g_h2h);
    cudaGetSymbolAddress((void**)&p_hh,  g_hh);
    cudaGetSymbolAddress((void**)&p_wph, g_wph);

    PFN_encodeTiled enc = nullptr;
    cudaGetDriverEntryPoint("cuTensorMapEncodeTiled", (void**)&enc, cudaEnableDefault);

    CUtensorMap mA1 = make_map(enc, p_xh,  FIN, NN);
    CUtensorMap mB1 = make_map(enc, p_w1h, FIN, F1);
    CUtensorMap mA2 = make_map(enc, p_o1h, F1,  NN);
    CUtensorMap mB2 = make_map(enc, p_w2h, F1,  F2);
    CUtensorMap mA3 = make_map(enc, p_hh,  F2,  NN);
    CUtensorMap mB3 = make_map(enc, p_wph, F2, PHID);

    cudaFuncSetAttribute(hgemm_tma, cudaFuncAttributeMaxDynamicSharedMemorySize, TG_SMEM);

    static cudaStream_t s1 = nullptr;
    static cudaEvent_t evF1 = nullptr, evJ1 = nullptr, evA1lo = nullptr,
                       evS1a = nullptr, evA2lo = nullptr, evA2hi = nullptr,
                       evJ2 = nullptr;
    if (!s1) {
        cudaStreamCreateWithFlags(&s1, cudaStreamNonBlocking);
        cudaEventCreateWithFlags(&evF1,  cudaEventDisableTiming);
        cudaEventCreateWithFlags(&evJ1,  cudaEventDisableTiming);
        cudaEventCreateWithFlags(&evA1lo, cudaEventDisableTiming);
        cudaEventCreateWithFlags(&evS1a, cudaEventDisableTiming);
        cudaEventCreateWithFlags(&evA2lo, cudaEventDisableTiming);
        cudaEventCreateWithFlags(&evA2hi, cudaEventDisableTiming);
        cudaEventCreateWithFlags(&evJ2,  cudaEventDisableTiming);
    }

    // ---- fork 1: CSR build + later-weight casts beside GEMM1 path ----
    cudaEventRecord(evF1, 0);
    cudaStreamWaitEvent(s1, evF1, 0);
    k_castT<<<(F1 * F2 + 255) / 256, 256, 0, s1>>>(W2, p_w2h, F1, F2);
    k_castT<<<(F2 * PHID + 255) / 256, 256, 0, s1>>>(Wp1, p_wph, F2, PHID);
    k_deg_init <<<(NN + 255) / 256, 256, 0, s1>>>(NN);
    k_deg_count<<<(EE + 255) / 256, 256, 0, s1>>>(dst, EE);
    k_scan<<<1, 1024, 0, s1>>>(NN);
    k_fill<<<(ETOT + 255) / 256, 256, 0, s1>>>(src, dst, EE, NN);
    cudaEventRecord(evJ1, s1);

    // ---- main: zero logits, casts -> GEMM1 (fp16 out + fused ss1/sd1) ----
    k_zero4<<<(NN * HH1 + 255) / 256, 256>>>(p_ss1, p_sd1, p_ss2, p_sd2, NN * HH1, NN);
    k_cast <<<(NN * FIN + 255) / 256, 256>>>(x, p_xh, NN * FIN);
    k_castT<<<(FIN * F1 + 255) / 256, 256>>>(W1, p_w1h, FIN, F1);
    hgemm_tma<<<dim3(F1 / 128, TLO + THI), 256, TG_SMEM>>>(mA1, mB1, nullptr, p_h1h,
                                                           NN, F1, FIN, 0,
                                                           p_ss1, p_sd1, as1, ad1);
    cudaStreamWaitEvent(0, evJ1, 0);

    // ---- agg1 split-pipeline with GEMM2 (fp16 out + fused ss2/sd2) ----
    k_agg<HH1, HD, 4><<<NSPLIT, 256>>>(p_h1h, p_ss1, p_sd1, b1, nullptr, p_o1h, 0);
    cudaEventRecord(evA1lo, 0);
    cudaStreamWaitEvent(s1, evA1lo, 0);
    hgemm_tma<<<dim3(F2 / 128, TLO), 256, TG_SMEM, s1>>>(mA2, mB2, nullptr, p_h2h,
                                                         NN, F2, F1, 0,
                                                         p_ss2, p_sd2, as2, ad2);
    cudaEventRecord(evS1a, s1);

    k_agg<HH1, HD, 4><<<NN - NSPLIT, 256>>>(p_h1h, p_ss1, p_sd1, b1, nullptr, p_o1h, NSPLIT);
    hgemm_tma<<<dim3(F2 / 128, THI), 256, TG_SMEM>>>(mA2, mB2, nullptr, p_h2h,
                                                     NN, F2, F1, TLO,
                                                     p_ss2, p_sd2, as2, ad2);
    cudaStreamWaitEvent(0, evS1a, 0);

    // ---- agg2 split-pipeline with GEMM3 + infl ----
    k_agg<1, F2, 1><<<NSPLIT, 256>>>(p_h2h, p_ss2, p_sd2, b2, out_h, p_hh, 0);
    cudaEventRecord(evA2lo, 0);
    cudaStreamWaitEvent(s1, evA2lo, 0);
    hgemm_tma<<<dim3(PHID / 128, TLO), 256, TG_SMEM, s1>>>(mA3, mB3, p_y, nullptr,
                                                           NN, PHID, F2, 0,
                                                           nullptr, nullptr, nullptr, nullptr);
    k_infl<<<(NSPLIT * 32 + 255) / 256, 256, 0, s1>>>(p_y, bp1, Wp2, bp2, out_i, NSPLIT);

    k_agg<1, F2, 1><<<NN - NSPLIT, 256>>>(p_h2h, p_ss2, p_sd2, b2, out_h, p_hh, NSPLIT);
    cudaEventRecord(evA2hi, 0);

    // side: graph mean (needs full out_h)
    cudaStreamWaitEvent(s1, evA2hi, 0);
    k_zero_gf<<<1, F2, 0, s1>>>(out_g);
    k_colsum<<<160, F2, 0, s1>>>(out_h, out_g);
    k_scale_gf<<<1, F2, 0, s1>>>(out_g);
    cudaEventRecord(evJ2, s1);

    // main: GEMM3_hi + infl_hi
    hgemm_tma<<<dim3(PHID / 128, THI), 256, TG_SMEM>>>(mA3, mB3, p_y, nullptr,
                                                       NN, PHID, F2, TLO,
                                                       nullptr, nullptr, nullptr, nullptr);
    k_infl<<<((NN - NSPLIT) * 32 + 255) / 256, 256>>>(p_y + (size_t)NSPLIT * PHID, bp1, Wp2, bp2,
                                                      out_i + NSPLIT, NN - NSPLIT);
    cudaStreamWaitEvent(0, evJ2, 0);
}

// round 12
// speedup vs baseline: 1.3301x; 1.0786x over previous
#include <cuda_runtime.h>
#include <cuda.h>
#include <cuda_fp16.h>
#include <math.h>
#include <cstdint>

#define NN   20000
#define EE   320000
#define ETOT 340000
#define FIN  384
#define F1   1024
#define HH1  4
#define HD   256
#define F2   256
#define PHID 128
#define NSPLIT 10112          // 79 row tiles of 128; divisible by 4
#define TLO 79
#define THI 78                // ceil(20000/128)=157 total tiles

// ---------------- scratch (static device globals; no runtime alloc) ----------
__device__ float g_yp[NN];            // influence partial (atomic accum)
__device__ float g_ss1[NN * HH1];
__device__ float g_sd1[NN * HH1];
__device__ float g_ss2[NN];
__device__ float g_sd2[NN];
__device__ int   g_deg[NN];
__device__ int   g_off[NN + 1];
__device__ int   g_cur[NN];
__device__ int   g_csrc[ETOT];
// fp16 planes (A row-major [M,K]; B transposed [N,K])
__device__ __align__(128) __half g_xh [(size_t)NN * FIN];
__device__ __align__(128) __half g_w1h[(size_t)F1 * FIN];
__device__ __align__(128) __half g_h1h[(size_t)NN * F1];
__device__ __align__(128) __half g_o1h[(size_t)NN * F1];
__device__ __align__(128) __half g_w2h[(size_t)F2 * F1];
__device__ __align__(128) __half g_h2h[(size_t)NN * F2];
__device__ __align__(128) __half g_hh [(size_t)NN * F2];
__device__ __align__(128) __half g_wph[(size_t)PHID * F2];

// ---------------- helpers ----------------
__device__ __forceinline__ uint32_t smem_u32(const void* p) {
    uint32_t a;
    asm("{ .reg .u64 t; cvta.to.shared.u64 t, %1; cvt.u32.u64 %0, t; }" : "=r"(a) : "l"(p));
    return a;
}
__device__ __forceinline__ void ldm4(uint32_t* r, uint32_t a) {
    asm volatile("ldmatrix.sync.aligned.m8n8.x4.shared.b16 {%0,%1,%2,%3}, [%4];"
                 : "=r"(r[0]), "=r"(r[1]), "=r"(r[2]), "=r"(r[3]) : "r"(a));
}
__device__ __forceinline__ void mma16816(float* c, const uint32_t* a, uint32_t b0, uint32_t b1) {
    asm volatile("mma.sync.aligned.m16n8k16.row.col.f32.f16.f16.f32 "
                 "{%0,%1,%2,%3}, {%4,%5,%6,%7}, {%8,%9}, {%0,%1,%2,%3};"
                 : "+f"(c[0]), "+f"(c[1]), "+f"(c[2]), "+f"(c[3])
                 : "r"(a[0]), "r"(a[1]), "r"(a[2]), "r"(a[3]), "r"(b0), "r"(b1));
}
#define MBARRIER_INIT(mb, c) \
    asm volatile("mbarrier.init.shared.b64 [%0], %1;" :: "r"((uint32_t)(mb)), "r"((uint32_t)(c)) : "memory")
#define MBARRIER_EXPECT_TX(mb, b) \
    asm volatile("mbarrier.arrive.expect_tx.shared.b64 _, [%0], %1;" \
                 :: "r"((uint32_t)(mb)), "r"((uint32_t)(b)) : "memory")
#define MBARRIER_WAIT_PARITY(mb, par) do { \
    uint32_t _m = (uint32_t)(mb), _p = (uint32_t)(par), _d; \
    asm volatile("{\n\t.reg .pred p;\n\t" \
        "mbarrier.try_wait.parity.acquire.cta.shared::cta.b64 p, [%1], %2;\n\t" \
        "selp.b32 %0, 1, 0, p;\n\t}" : "=r"(_d) : "r"(_m), "r"(_p) : "memory"); \
    if (!_d) { \
        asm volatile("{\n\t.reg .pred P1;\n\tWL_%=:\n\t" \
            "mbarrier.try_wait.parity.acquire.cta.shared::cta.b64 P1, [%0], %1, 0x989680;\n\t" \
            "@P1 bra.uni WD_%=;\n\tbra.uni WL_%=;\n\tWD_%=:\n\t}" \
            :: "r"(_m), "r"(_p) : "memory"); \
    } } while (0)
__device__ __forceinline__ void tma2d(uint32_t dst, const void* map, int x, int y, uint32_t mb) {
    asm volatile(
        "cp.async.bulk.tensor.2d.shared::cta.global.tile.mbarrier::complete_tx::bytes "
        "[%0], [%1, {%2, %3}], [%4];"
        :: "r"(dst), "l"(map), "r"(x), "r"(y), "r"(mb) : "memory");
}
#define SW128(o) ((o) ^ (((o) >> 3) & 0x70u))

// ---------------- fp16 cast + zero kernels ----------------
__global__ void k_cast(const float* __restrict__ in, __half* __restrict__ o, int total) {
    int i = blockIdx.x * blockDim.x + threadIdx.x;
    if (i < total) o[i] = __float2half_rn(in[i]);
}
__global__ void k_castT(const float* __restrict__ W, __half* __restrict__ o, int K, int N) {
    int i = blockIdx.x * blockDim.x + threadIdx.x;
    if (i >= K * N) return;
    int k = i / N, n = i % N;
    o[(size_t)n * K + k] = __float2half_rn(W[i]);
}
__global__ void k_zero5(float* a, float* b, float* c, float* d, float* e, int n1, int n2) {
    int i = blockIdx.x * blockDim.x + threadIdx.x;
    if (i < n1) { a[i] = 0.f; b[i] = 0.f; }
    if (i < n2) { c[i] = 0.f; d[i] = 0.f; e[i] = 0.f; }
}

// ============== TMA HMMA GEMM: C[M,N] = A[M,K] @ B[N,K]^T ====================
// fp16 in, fp32 accum. Outputs: fp32 C and/or fp16 Ch (non-null ones).
// Optional fused attention logits (ss/sd/av/bv) or fused influence partial
// (yp/bp1/wp2: p[m] += sum_c relu(C[m,c]+bp1[c])*wp2[c], valid when N==128).
#define TG_STAGE 32768
#define TG_SMEM (1024 + 3 * TG_STAGE)

__global__ void __launch_bounds__(256, 2)
hgemm_tma(const __grid_constant__ CUtensorMap mA,
          const __grid_constant__ CUtensorMap mB,
          float* __restrict__ C, __half* __restrict__ Ch, int M, int N, int K, int ytile0,
          float* __restrict__ ss, float* __restrict__ sd,
          const float* __restrict__ av, const float* __restrict__ bv,
          float* __restrict__ yp, const float* __restrict__ bp1,
          const float* __restrict__ wp2) {
    extern __shared__ unsigned char smraw[];
    const uint32_t base0 = (smem_u32(smraw) + 1023u) & ~1023u;
    const uint32_t mbb = base0;
    const uint32_t tile0 = base0 + 1024;
    const int tid = threadIdx.x, wid = tid >> 5, lane = tid & 31;
    const int bm = (blockIdx.y + ytile0) * 128, bn = blockIdx.x * 128;
    const int wr = (wid >> 1) * 32, wn = (wid & 1) * 64;
    const int nc = K >> 6;

    if (tid == 0) {
        MBARRIER_INIT(mbb + 0, 1);
        MBARRIER_INIT(mbb + 8, 1);
        MBARRIER_INIT(mbb + 16, 1);
    }
    __syncthreads();

    if (tid == 0) {
#pragma unroll
        for (int s = 0; s < 2; s++) {
            uint32_t mb = mbb + 8u * s;
            uint32_t t = tile0 + (uint32_t)s * TG_STAGE;
            MBARRIER_EXPECT_TX(mb, TG_STAGE);
            tma2d(t,          &mA, s * 64, bm, mb);
            tma2d(t + 16384u, &mB, s * 64, bn, mb);
        }
    }

    float acc[2][8][4];
#pragma unroll
    for (int a = 0; a < 2; a++)
#pragma unroll
        for (int b = 0; b < 8; b++)
#pragma unroll
            for (int c = 0; c < 4; c++) acc[a][b][c] = 0.f;

    for (int i = 0; i < nc; i++) {
        const int b = i % 3;
        MBARRIER_WAIT_PARITY(mbb + 8u * b, (i / 3) & 1);
        __syncthreads();
        if (tid == 0 && i + 2 < nc) {
            const int nb = (i + 2) % 3;
            uint32_t mb = mbb + 8u * nb;
            uint32_t t = tile0 + (uint32_t)nb * TG_STAGE;
            MBARRIER_EXPECT_TX(mb, TG_STAGE);
            tma2d(t,          &mA, (i + 2) * 64, bm, mb);
            tma2d(t + 16384u, &mB, (i + 2) * 64, bn, mb);
        }

        const uint32_t tA = tile0 + (uint32_t)b * TG_STAGE;
        const uint32_t tB = tA + 16384u;
        const int gq = lane >> 3;
#pragma unroll
        for (int ks = 0; ks < 4; ks++) {
            uint32_t ar[2][4], br[4][4];
#pragma unroll
            for (int mt = 0; mt < 2; mt++) {
                uint32_t lin = (uint32_t)(wr + mt * 16 + (lane & 15)) * 128u
                             + (uint32_t)(ks * 32 + (lane >> 4) * 16);
                ldm4(ar[mt], tA + SW128(lin));
            }
#pragma unroll
            for (int bt = 0; bt < 4; bt++) {
                uint32_t lin = (uint32_t)(wn + bt * 16 + ((gq >> 1) << 3) + (lane & 7)) * 128u
                             + (uint32_t)(ks * 32 + (gq & 1) * 16);
                ldm4(br[bt], tB + SW128(lin));
            }
#pragma unroll
            for (int mt = 0; mt < 2; mt++)
#pragma unroll
                for (int j = 0; j < 8; j++) {
                    const int bt = j >> 1, p0 = (j & 1) * 2;
                    mma16816(acc[mt][j], ar[mt], br[bt][p0], br[bt][p0 + 1]);
                }
        }
    }

    // epilogue: fp32 and/or fp16 stores
#pragma unroll
    for (int mt = 0; mt < 2; mt++) {
        int m0 = bm + wr + mt * 16 + (lane >> 2);
#pragma unroll
        for (int j = 0; j < 8; j++) {
            int n0 = bn + wn + j * 8 + (lane & 3) * 2;
            if (C) {
                if (m0 < M)
                    *(float2*)&C[(size_t)m0 * N + n0] = make_float2(acc[mt][j][0], acc[mt][j][1]);
                if (m0 + 8 < M)
                    *(float2*)&C[(size_t)(m0 + 8) * N + n0] = make_float2(acc[mt][j][2], acc[mt][j][3]);
            }
            if (Ch) {
                if (m0 < M)
                    *(__half2*)&Ch[(size_t)m0 * N + n0] =
                        __floats2half2_rn(acc[mt][j][0], acc[mt][j][1]);
                if (m0 + 8 < M)
                    *(__half2*)&Ch[(size_t)(m0 + 8) * N + n0] =
                        __floats2half2_rn(acc[mt][j][2], acc[mt][j][3]);
            }
        }
    }

    // fused attention-logit partials
    if (ss) {
        const int Hh = N >> 8;
        const int h = bn >> 8;
        const int cb0 = (bn & 255) + wn + (lane & 3) * 2;
#pragma unroll
        for (int mt = 0; mt < 2; mt++) {
            int m0 = bm + wr + mt * 16 + (lane >> 2);
            float ps0 = 0.f, pd0 = 0.f, ps1 = 0.f, pd1 = 0.f;
#pragma unroll
            for (int j = 0; j < 8; j++) {
                int cb = cb0 + j * 8;
                float a0 = av[h * 256 + cb], a1 = av[h * 256 + cb + 1];
                float d0 = bv[h * 256 + cb], d1 = bv[h * 256 + cb + 1];
                ps0 += acc[mt][j][0] * a0 + acc[mt][j][1] * a1;
                pd0 += acc[mt][j][0] * d0 + acc[mt][j][1] * d1;
                ps1 += acc[mt][j][2] * a0 + acc[mt][j][3] * a1;
                pd1 += acc[mt][j][2] * d0 + acc[mt][j][3] * d1;
            }
#pragma unroll
            for (int o = 1; o < 4; o <<= 1) {
                ps0 += __shfl_xor_sync(0xffffffffu, ps0, o);
                pd0 += __shfl_xor_sync(0xffffffffu, pd0, o);
                ps1 += __shfl_xor_sync(0xffffffffu, ps1, o);
                pd1 += __shfl_xor_sync(0xffffffffu, pd1, o);
            }
            if ((lane & 3) == 0) {
                if (m0 < M) {
                    atomicAdd(&ss[m0 * Hh + h], ps0);
                    atomicAdd(&sd[m0 * Hh + h], pd0);
                }
                if (m0 + 8 < M) {
                    atomicAdd(&ss[(m0 + 8) * Hh + h], ps1);
                    atomicAdd(&sd[(m0 + 8) * Hh + h], pd1);
                }
            }
        }
    }

    // fused influence partial (N == 128, bn == 0)
    if (yp) {
#pragma unroll
        for (int mt = 0; mt < 2; mt++) {
            int m0 = bm + wr + mt * 16 + (lane >> 2);
            float p0 = 0.f, p1 = 0.f;
#pragma unroll
            for (int j = 0; j < 8; j++) {
                int n0 = wn + j * 8 + (lane & 3) * 2;
                float w0 = wp2[n0], w1 = wp2[n0 + 1];
                float b0 = bp1[n0], b1 = bp1[n0 + 1];
                p0 += fmaxf(acc[mt][j][0] + b0, 0.f) * w0 + fmaxf(acc[mt][j][1] + b1, 0.f) * w1;
                p1 += fmaxf(acc[mt][j][2] + b0, 0.f) * w0 + fmaxf(acc[mt][j][3] + b1, 0.f) * w1;
            }
#pragma unroll
            for (int o = 1; o < 4; o <<= 1) {
                p0 += __shfl_xor_sync(0xffffffffu, p0, o);
                p1 += __shfl_xor_sync(0xffffffffu, p1, o);
            }
            if ((lane & 3) == 0) {
                if (m0 < M) atomicAdd(&yp[m0], p0);
                if (m0 + 8 < M) atomicAdd(&yp[m0 + 8], p1);
            }
        }
    }
}

// ---------------- CSR build ----------------
__global__ void k_deg_init(int n) {
    int i = blockIdx.x * blockDim.x + threadIdx.x;
    if (i < n) g_deg[i] = 1;
}
__global__ void k_deg_count(const int* __restrict__ dst, int e) {
    int i = blockIdx.x * blockDim.x + threadIdx.x;
    if (i < e) atomicAdd(&g_deg[dst[i]], 1);
}
__global__ void k_scan(int n) {
    __shared__ int sums[1024];
    int tid = threadIdx.x;
    int chunk = (n + 1023) / 1024;
    int lo = tid * chunk, hi = min(lo + chunk, n);
    int s = 0;
    for (int i = lo; i < hi; i++) s += g_deg[i];
    sums[tid] = s;
    __syncthreads();
    for (int d = 1; d < 1024; d <<= 1) {
        int v = (tid >= d) ? sums[tid - d] : 0;
        __syncthreads();
        sums[tid] += v;
        __syncthreads();
    }
    int base = (tid == 0) ? 0 : sums[tid - 1];
    for (int i = lo; i < hi; i++) {
        g_off[i] = base;
        g_cur[i] = base;
        base += g_deg[i];
    }
    if (tid == 1023) g_off[n] = sums[1023];
}
__global__ void k_fill(const int* __restrict__ src, const int* __restrict__ dst, int e, int n) {
    int i = blockIdx.x * blockDim.x + threadIdx.x;
    if (i >= e + n) return;
    int s, d;
    if (i < e) { s = src[i]; d = dst[i]; }
    else       { s = i - e;  d = i - e; }
    int pos = atomicAdd(&g_cur[d], 1);
    g_csrc[pos] = s;
}

// ---------------- grouped per-dst softmax + aggregation ----------------
// 256/GSZ nodes per block; GSZ-thread groups with named barriers.
// fp16 gather: PH = H*C/GSZ halves per thread (8 -> uint4, 4 -> uint2).
__device__ __forceinline__ float lrelu(float x) { return x > 0.f ? x : 0.2f * x; }
__device__ __forceinline__ void acc8(float* a, uint4 v, float w) {
    float2 f;
    f = __half22float2(*(__half2*)&v.x); a[0] += f.x * w; a[1] += f.y * w;
    f = __half22float2(*(__half2*)&v.y); a[2] += f.x * w; a[3] += f.y * w;
    f = __half22float2(*(__half2*)&v.z); a[4] += f.x * w; a[5] += f.y * w;
    f = __half22float2(*(__half2*)&v.w); a[6] += f.x * w; a[7] += f.y * w;
}
__device__ __forceinline__ void acc4(float* a, uint2 v, float w) {
    float2 f;
    f = __half22float2(*(__half2*)&v.x); a[0] += f.x * w; a[1] += f.y * w;
    f = __half22float2(*(__half2*)&v.y); a[2] += f.x * w; a[3] += f.y * w;
}

template <int H, int C, int GSZ>
__global__ void __launch_bounds__(256)
k_agg(const __half* __restrict__ feat, const float* __restrict__ ss,
      const float* __restrict__ sd, const float* __restrict__ bias,
      float* __restrict__ out, __half* __restrict__ oh, int d0) {
    constexpr int NG  = 256 / GSZ;
    constexpr int CAP = 64;
    constexpr int HC  = H * C;
    constexpr int PH  = HC / GSZ;       // 8 (agg1) or 4 (agg2)
    const int t = threadIdx.x;
    const int g = t / GSZ, gt = t % GSZ;
    const int gw = gt >> 5, lane = gt & 31;
    const int d = d0 + blockIdx.x * NG + g;
    const int base = g_off[d], deg = g_off[d + 1] - base;
    const int capped = min(deg, CAP);
    const int barid = g + 1;

    __shared__ float s_e[NG][CAP * H];
    __shared__ int   s_idx[NG][CAP];
    __shared__ float s_m[NG][H], s_inv[NG][H];

#define GBAR() asm volatile("bar.sync %0, %1;" :: "r"(barid), "r"((int)GSZ) : "memory")

    // Phase A: cache src indices + raw leaky-relu logits
    {
        const int jj = (H == 1) ? gt : (gt >> 2);
        const int h  = (H == 1) ? 0 : (gt & 3);
        const float sdv = sd[d * H + h];
        for (int j0 = 0; j0 < capped; j0 += GSZ / H) {
            int j = j0 + jj;
            if (j < capped) {
                int s = g_csrc[base + j];
                if (h == 0) s_idx[g][j] = s;
                s_e[g][j * H + h] = lrelu(ss[s * H + h] + sdv);
            }
        }
    }
    GBAR();

    // Phase B: per-head max + denominator (warp gw handles head gw)
    if (gw < H) {
        const int h = gw;
        const float sdv = sd[d * H + h];
        float mx = -1e30f;
        for (int j = lane; j < capped; j += 32) mx = fmaxf(mx, s_e[g][j * H + h]);
        for (int j = CAP + lane; j < deg; j += 32) {
            int s = g_csrc[base + j];
            mx = fmaxf(mx, lrelu(ss[s * H + h] + sdv));
        }
#pragma unroll
        for (int o = 16; o; o >>= 1) mx = fmaxf(mx, __shfl_xor_sync(0xffffffffu, mx, o));
        float sm = 0.f;
        for (int j = lane; j < capped; j += 32) sm += expf(s_e[g][j * H + h] - mx);
        for (int j = CAP + lane; j < deg; j += 32) {
            int s = g_csrc[base + j];
            sm += expf(lrelu(ss[s * H + h] + sdv) - mx);
        }
#pragma unroll
        for (int o = 16; o; o >>= 1) sm += __shfl_xor_sync(0xffffffffu, sm, o);
        if (lane == 0) { s_m[g][h] = mx; s_inv[g][h] = 1.f / (sm + 1e-16f); }
    }
    GBAR();

    // Phase C: logits -> normalized weights in place
    {
        const int jj = (H == 1) ? gt : (gt >> 2);
        const int h  = (H == 1) ? 0 : (gt & 3);
        const float mh = s_m[g][h], iv = s_inv[g][h];
        for (int j0 = 0; j0 < capped; j0 += GSZ / H) {
            int j = j0 + jj;
            if (j < capped) s_e[g][j * H + h] = expf(s_e[g][j * H + h] - mh) * iv;
        }
    }
    GBAR();

    const int hh = (gt * PH) / C;   // warp-uniform
    float acc[PH];
#pragma unroll
    for (int k = 0; k < PH; k++) acc[k] = 0.f;
    const float* we = &s_e[g][0];
    const int* sidx = &s_idx[g][0];

    // Phase D: vector gather with 4-deep prefetch
    if (PH == 8) {
        const __half* fb = feat + gt * 8;
        uint4 b0 = make_uint4(0, 0, 0, 0), b1 = b0, b2 = b0, b3 = b0;
        if (capped > 0) b0 = *(const uint4*)(fb + (size_t)sidx[0] * HC);
        if (capped > 1) b1 = *(const uint4*)(fb + (size_t)sidx[1] * HC);
        if (capped > 2) b2 = *(const uint4*)(fb + (size_t)sidx[2] * HC);
        if (capped > 3) b3 = *(const uint4*)(fb + (size_t)sidx[3] * HC);
        int j = 0;
        for (; j + 4 <= capped; j += 4) {
            float w0 = we[(j + 0) * H + hh], w1 = we[(j + 1) * H + hh];
            float w2 = we[(j + 2) * H + hh], w3 = we[(j + 3) * H + hh];
            uint4 v0 = b0, v1 = b1, v2 = b2, v3 = b3;
            if (j + 4 < capped) b0 = *(const uint4*)(fb + (size_t)sidx[j + 4] * HC);
            if (j + 5 < capped) b1 = *(const uint4*)(fb + (size_t)sidx[j + 5] * HC);
            if (j + 6 < capped) b2 = *(const uint4*)(fb + (size_t)sidx[j + 6] * HC);
            if (j + 7 < capped) b3 = *(const uint4*)(fb + (size_t)sidx[j + 7] * HC);
            acc8(acc, v0, w0); acc8(acc, v1, w1); acc8(acc, v2, w2); acc8(acc, v3, w3);
        }
        if (j     < capped) acc8(acc, b0, we[(j + 0) * H + hh]);
        if (j + 1 < capped) acc8(acc, b1, we[(j + 1) * H + hh]);
        if (j + 2 < capped) acc8(acc, b2, we[(j + 2) * H + hh]);
    } else {
        const __half* fb = feat + gt * 4;
        uint2 b0 = make_uint2(0, 0), b1 = b0, b2 = b0, b3 = b0;
        if (capped > 0) b0 = *(const uint2*)(fb + (size_t)sidx[0] * HC);
        if (capped > 1) b1 = *(const uint2*)(fb + (size_t)sidx[1] * HC);
        if (capped > 2) b2 = *(const uint2*)(fb + (size_t)sidx[2] * HC);
        if (capped > 3) b3 = *(const uint2*)(fb + (size_t)sidx[3] * HC);
        int j = 0;
        for (; j + 4 <= capped; j += 4) {
            float w0 = we[(j + 0) * H + hh], w1 = we[(j + 1) * H + hh];
            float w2 = we[(j + 2) * H + hh], w3 = we[(j + 3) * H + hh];
            uint2 v0 = b0, v1 = b1, v2 = b2, v3 = b3;
            if (j + 4 < capped) b0 = *(const uint2*)(fb + (size_t)sidx[j + 4] * HC);
            if (j + 5 < capped) b1 = *(const uint2*)(fb + (size_t)sidx[j + 5] * HC);
            if (j + 6 < capped) b2 = *(const uint2*)(fb + (size_t)sidx[j + 6] * HC);
            if (j + 7 < capped) b3 = *(const uint2*)(fb + (size_t)sidx[j + 7] * HC);
            acc4(acc, v0, w0); acc4(acc, v1, w1); acc4(acc, v2, w2); acc4(acc, v3, w3);
        }
        if (j     < capped) acc4(acc, b0, we[(j + 0) * H + hh]);
        if (j + 1 < capped) acc4(acc, b1, we[(j + 1) * H + hh]);
        if (j + 2 < capped) acc4(acc, b2, we[(j + 2) * H + hh]);
    }

    // Phase E: overflow edges (deg > CAP) — rare correctness path
    if (deg > CAP) {
        const float mh = s_m[g][hh], iv = s_inv[g][hh];
        const float sdv = sd[d * H + hh];
        for (int j = CAP; j < deg; j++) {
            int s = g_csrc[base + j];
            float w = expf(lrelu(ss[s * H + hh] + sdv) - mh) * iv;
            if (PH == 8) acc8(acc, *(const uint4*)(feat + (size_t)s * HC + gt * 8), w);
            else         acc4(acc, *(const uint2*)(feat + (size_t)s * HC + gt * 4), w);
        }
    }

    // epilogue
    const int c0 = gt * PH;
    float vv[PH];
#pragma unroll
    for (int k = 0; k < PH; k++) {
        float v = acc[k] + bias[c0 + k];
        vv[k] = v > 0.f ? v : expm1f(v);
    }
    if (out) {
#pragma unroll
        for (int k = 0; k < PH; k += 2)
            *(float2*)&out[(size_t)d * HC + c0 + k] = make_float2(vv[k], vv[k + 1]);
    }
#pragma unroll
    for (int k = 0; k < PH; k += 2)
        *(__half2*)&oh[(size_t)d * HC + c0 + k] = __floats2half2_rn(vv[k], vv[k + 1]);
#undef GBAR
}

// ---------------- graph mean + sigmoid ----------------
__global__ void k_zero_gf(float* gf) { gf[threadIdx.x] = 0.f; }
__global__ void k_colsum(const float* __restrict__ h, float* __restrict__ gf) {
    float acc = 0.f;
    int t = threadIdx.x;
    for (int r = blockIdx.x; r < NN; r += gridDim.x) acc += h[(size_t)r * F2 + t];
    atomicAdd(&gf[t], acc);
}
__global__ void k_scale_gf(float* gf) { gf[threadIdx.x] *= (1.0f / (float)NN); }

__global__ void k_sigmoid(const float* __restrict__ yp, const float* __restrict__ bp2,
                          float* __restrict__ infl, int n, int i0) {
    int i = blockIdx.x * blockDim.x + threadIdx.x;
    if (i < n) infl[i0 + i] = 1.f / (1.f + expf(-(yp[i0 + i] + bp2[0])));
}

// ---------------- host: tensor-map builder ----------------
typedef CUresult (*PFN_encodeTiled)(
    CUtensorMap*, CUtensorMapDataType, cuuint32_t, void*,
    const cuuint64_t*, const cuuint64_t*, const cuuint32_t*, const cuuint32_t*,
    CUtensorMapInterleave, CUtensorMapSwizzle, CUtensorMapL2promotion,
    CUtensorMapFloatOOBfill);

static CUtensorMap make_map(PFN_encodeTiled enc, void* base, int K, int rows) {
    CUtensorMap m;
    cuuint64_t dims[2]    = {(cuuint64_t)K, (cuuint64_t)rows};
    cuuint64_t strides[1] = {(cuuint64_t)K * 2};
    cuuint32_t box[2]     = {64, 128};
    cuuint32_t es[2]      = {1, 1};
    enc(&m, CU_TENSOR_MAP_DATA_TYPE_FLOAT16, 2, base, dims, strides, box, es,
        CU_TENSOR_MAP_INTERLEAVE_NONE, CU_TENSOR_MAP_SWIZZLE_128B,
        CU_TENSOR_MAP_L2_PROMOTION_L2_128B, CU_TENSOR_MAP_FLOAT_OOB_FILL_NONE);
    return m;
}

// ---------------- launch ----------------
extern "C" void kernel_launch(void* const* d_in, const int* in_sizes, int n_in,
                              void* d_out, int out_size) {
    const float* x   = (const float*)d_in[0];
    const int*   eidx = (const int*)d_in[1];
    const float* W1  = (const float*)d_in[2];
    const float* as1 = (const float*)d_in[3];
    const float* ad1 = (const float*)d_in[4];
    const float* b1  = (const float*)d_in[5];
    const float* W2  = (const float*)d_in[6];
    const float* as2 = (const float*)d_in[7];
    const float* ad2 = (const float*)d_in[8];
    const float* b2  = (const float*)d_in[9];
    const float* Wp1 = (const float*)d_in[10];
    const float* bp1 = (const float*)d_in[11];
    const float* Wp2 = (const float*)d_in[12];
    const float* bp2 = (const float*)d_in[13];

    const int* src = eidx;
    const int* dst = eidx + EE;

    float* out   = (float*)d_out;
    float* out_h = out;
    float* out_g = out + (size_t)NN * F2;
    float* out_i = out_g + F2;

    float *p_yp, *p_ss1, *p_sd1, *p_ss2, *p_sd2;
    __half *p_xh, *p_w1h, *p_h1h, *p_o1h, *p_w2h, *p_h2h, *p_hh, *p_wph;
    cudaGetSymbolAddress((void**)&p_yp, g_yp);
    cudaGetSymbolAddress((void**)&p_ss1, g_ss1);
    cudaGetSymbolAddress((void**)&p_sd1, g_sd1);
    cudaGetSymbolAddress((void**)&p_ss2, g_ss2);
    cudaGetSymbolAddress((void**)&p_sd2, g_sd2);
    cudaGetSymbolAddress((void**)&p_xh,  g_xh);
    cudaGetSymbolAddress((void**)&p_w1h, g_w1h);
    cudaGetSymbolAddress((void**)&p_h1h, g_h1h);
    cudaGetSymbolAddress((void**)&p_o1h, g_o1h);
    cudaGetSymbolAddress((void**)&p_w2h, g_w2h);
    cudaGetSymbolAddress((void**)&p_h2h, g_h2h);
    cudaGetSymbolAddress((void**)&p_hh,  g_hh);
    cudaGetSymbolAddress((void**)&p_wph, g_wph);

    PFN_encodeTiled enc = nullptr;
    cudaGetDriverEntryPoint("cuTensorMapEncodeTiled", (void**)&enc, cudaEnableDefault);

    CUtensorMap mA1 = make_map(enc, p_xh,  FIN, NN);
    CUtensorMap mB1 = make_map(enc, p_w1h, FIN, F1);
    CUtensorMap mA2 = make_map(enc, p_o1h, F1,  NN);
    CUtensorMap mB2 = make_map(enc, p_w2h, F1,  F2);
    CUtensorMap mA3 = make_map(enc, p_hh,  F2,  NN);
    CUtensorMap mB3 = make_map(enc, p_wph, F2, PHID);

    cudaFuncSetAttribute(hgemm_tma, cudaFuncAttributeMaxDynamicSharedMemorySize, TG_SMEM);

    static cudaStream_t s1 = nullptr;
    static cudaEvent_t evF1 = nullptr, evW1 = nullptr, evJ1 = nullptr, evA1lo = nullptr,
                       evS1a = nullptr, evA2lo = nullptr, evA2hi = nullptr, evJ2 = nullptr;
    if (!s1) {
        cudaStreamCreateWithFlags(&s1, cudaStreamNonBlocking);
        cudaEventCreateWithFlags(&evF1,  cudaEventDisableTiming);
        cudaEventCreateWithFlags(&evW1,  cudaEventDisableTiming);
        cudaEventCreateWithFlags(&evJ1,  cudaEventDisableTiming);
        cudaEventCreateWithFlags(&evA1lo, cudaEventDisableTiming);
        cudaEventCreateWithFlags(&evS1a, cudaEventDisableTiming);
        cudaEventCreateWithFlags(&evA2lo, cudaEventDisableTiming);
        cudaEventCreateWithFlags(&evA2hi, cudaEventDisableTiming);
        cudaEventCreateWithFlags(&evJ2,  cudaEventDisableTiming);
    }

    // ---- fork 1: W1 cast first (GEMM1 dep), then W2/Wp1 casts + CSR ----
    cudaEventRecord(evF1, 0);
    cudaStreamWaitEvent(s1, evF1, 0);
    k_castT<<<(FIN * F1 + 255) / 256, 256, 0, s1>>>(W1, p_w1h, FIN, F1);
    cudaEventRecord(evW1, s1);
    k_castT<<<(F1 * F2 + 255) / 256, 256, 0, s1>>>(W2, p_w2h, F1, F2);
    k_castT<<<(F2 * PHID + 255) / 256, 256, 0, s1>>>(Wp1, p_wph, F2, PHID);
    k_deg_init <<<(NN + 255) / 256, 256, 0, s1>>>(NN);
    k_deg_count<<<(EE + 255) / 256, 256, 0, s1>>>(dst, EE);
    k_scan<<<1, 1024, 0, s1>>>(NN);
    k_fill<<<(ETOT + 255) / 256, 256, 0, s1>>>(src, dst, EE, NN);
    cudaEventRecord(evJ1, s1);

    // ---- main: zero logits+partial, cast x -> GEMM1 (fp16 out + fused ss1/sd1) ----
    k_zero5<<<(NN * HH1 + 255) / 256, 256>>>(p_ss1, p_sd1, p_ss2, p_sd2, p_yp, NN * HH1, NN);
    k_cast <<<(NN * FIN + 255) / 256, 256>>>(x, p_xh, NN * FIN);
    cudaStreamWaitEvent(0, evW1, 0);
    hgemm_tma<<<dim3(F1 / 128, TLO + THI), 256, TG_SMEM>>>(mA1, mB1, nullptr, p_h1h,
                                                           NN, F1, FIN, 0,
                                                           p_ss1, p_sd1, as1, ad1,
                                                           nullptr, nullptr, nullptr);
    cudaStreamWaitEvent(0, evJ1, 0);

    // ---- agg1 split-pipeline with GEMM2 (fp16 out + fused ss2/sd2) ----
    k_agg<HH1, HD, 128><<<NSPLIT / 2, 256>>>(p_h1h, p_ss1, p_sd1, b1, nullptr, p_o1h, 0);
    cudaEventRecord(evA1lo, 0);
    cudaStreamWaitEvent(s1, evA1lo, 0);
    hgemm_tma<<<dim3(F2 / 128, TLO), 256, TG_SMEM, s1>>>(mA2, mB2, nullptr, p_h2h,
                                                         NN, F2, F1, 0,
                                                         p_ss2, p_sd2, as2, ad2,
                                                         nullptr, nullptr, nullptr);
    cudaEventRecord(evS1a, s1);

    k_agg<HH1, HD, 128><<<(NN - NSPLIT) / 2, 256>>>(p_h1h, p_ss1, p_sd1, b1, nullptr, p_o1h, NSPLIT);
    hgemm_tma<<<dim3(F2 / 128, THI), 256, TG_SMEM>>>(mA2, mB2, nullptr, p_h2h,
                                                     NN, F2, F1, TLO,
                                                     p_ss2, p_sd2, as2, ad2,
                                                     nullptr, nullptr, nullptr);
    cudaStreamWaitEvent(0, evS1a, 0);

    // ---- agg2 split-pipeline with GEMM3 (fused influence partial) ----
    k_agg<1, F2, 64><<<NSPLIT / 4, 256>>>(p_h2h, p_ss2, p_sd2, b2, out_h, p_hh, 0);
    cudaEventRecord(evA2lo, 0);
    cudaStreamWaitEvent(s1, evA2lo, 0);
    hgemm_tma<<<dim3(PHID / 128, TLO), 256, TG_SMEM, s1>>>(mA3, mB3, nullptr, nullptr,
                                                           NN, PHID, F2, 0,
                                                           nullptr, nullptr, nullptr, nullptr,
                                                           p_yp, bp1, Wp2);
    k_sigmoid<<<(NSPLIT + 255) / 256, 256, 0, s1>>>(p_yp, bp2, out_i, NSPLIT, 0);

    k_agg<1, F2, 64><<<(NN - NSPLIT) / 4, 256>>>(p_h2h, p_ss2, p_sd2, b2, out_h, p_hh, NSPLIT);
    cudaEventRecord(evA2hi, 0);

    // side: graph mean (needs full out_h)
    cudaStreamWaitEvent(s1, evA2hi, 0);
    k_zero_gf<<<1, F2, 0, s1>>>(out_g);
    k_colsum<<<160, F2, 0, s1>>>(out_h, out_g);
    k_scale_gf<<<1, F2, 0, s1>>>(out_g);
    cudaEventRecord(evJ2, s1);

    // main: GEMM3_hi (fused influence) + sigmoid_hi
    hgemm_tma<<<dim3(PHID / 128, THI), 256, TG_SMEM>>>(mA3, mB3, nullptr, nullptr,
                                                       NN, PHID, F2, TLO,
                                                       nullptr, nullptr, nullptr, nullptr,
                                                       p_yp, bp1, Wp2);
    k_sigmoid<<<(NN - NSPLIT + 255) / 256, 256>>>(p_yp, bp2, out_i, NN - NSPLIT, NSPLIT);
    cudaStreamWaitEvent(0, evJ2, 0);
}